// round 1
// baseline (speedup 1.0000x reference)
#include <cuda_runtime.h>
#include <cuda_bf16.h>
#include <math.h>

// Problem constants
#define BB 2
#define TT 2048
#define EE 512
#define HH 8
#define HD 64
#define MM 64
#define LL 32
#define BH (BB*HH)

// Scratch (device globals; no runtime allocation)
__device__ float g_qkv[BB*TT*3*EE];      // 24 MB
__device__ float g_qland[BH*MM*HD];
__device__ float g_kland[BH*MM*HD];
__device__ float g_A[BH*MM*MM];
__device__ float g_z[BH*MM*MM];
__device__ float g_XZ[BH*MM*MM];
__device__ float g_T1[BH*MM*MM];
__device__ float g_sums[BH*2];           // [colsum_max, rowsum_max] per bh
__device__ float g_zB[BH*MM*HD];
__device__ float g_F[BH*TT*MM];          // 8 MB
__device__ float g_y[BB*TT*EE];          // 8 MB

// ---------------------------------------------------------------------------
// SGEMM with bias: C[M,N] = A[M,K] @ B[K,N] + bias[N]
// DST==0: write g_qkv, read A param. DST==1: read g_y, write C param.
// BM=BN=128, BK=8, TM=TN=8, 256 threads.
// ---------------------------------------------------------------------------
template<int DST>
__global__ __launch_bounds__(256)
void sgemm_bias(const float* __restrict__ Ain, const float* __restrict__ Bm,
                const float* __restrict__ bias, float* __restrict__ Cout,
                int Md, int Nd, int Kd) {
    const int BM = 128, BN = 128, BK = 8, TM = 8, TN = 8;
    __shared__ float As[BK*BM];
    __shared__ float Bs[BK*BN];

    const float* A = (DST == 0) ? Ain : g_y;
    float* C = (DST == 0) ? g_qkv : Cout;

    int bx = blockIdx.x;   // N tile
    int by = blockIdx.y;   // M tile
    int tid = threadIdx.x;

    int threadRow = tid / (BN / TN);  // 0..15
    int threadCol = tid % (BN / TN);  // 0..15

    const float* Aptr = A + (size_t)by * BM * Kd;
    const float* Bptr = Bm + (size_t)bx * BN;

    int innerRowA = tid / (BK / 4);   // 0..127
    int innerColA = tid % (BK / 4);   // 0..1
    int innerRowB = tid / (BN / 4);   // 0..7
    int innerColB = tid % (BN / 4);   // 0..31

    float acc[TM][TN];
    #pragma unroll
    for (int i = 0; i < TM; i++)
        #pragma unroll
        for (int j = 0; j < TN; j++) acc[i][j] = 0.0f;

    for (int k0 = 0; k0 < Kd; k0 += BK) {
        float4 a4 = *(const float4*)(Aptr + (size_t)innerRowA * Kd + k0 + innerColA * 4);
        As[(innerColA * 4 + 0) * BM + innerRowA] = a4.x;
        As[(innerColA * 4 + 1) * BM + innerRowA] = a4.y;
        As[(innerColA * 4 + 2) * BM + innerRowA] = a4.z;
        As[(innerColA * 4 + 3) * BM + innerRowA] = a4.w;
        float4 b4 = *(const float4*)(Bptr + (size_t)(k0 + innerRowB) * Nd + innerColB * 4);
        *(float4*)(Bs + innerRowB * BN + innerColB * 4) = b4;
        __syncthreads();

        #pragma unroll
        for (int k = 0; k < BK; k++) {
            float regM[TM], regN[TN];
            #pragma unroll
            for (int i = 0; i < TM; i++) regM[i] = As[k * BM + threadRow * TM + i];
            #pragma unroll
            for (int j = 0; j < TN; j++) regN[j] = Bs[k * BN + threadCol * TN + j];
            #pragma unroll
            for (int i = 0; i < TM; i++)
                #pragma unroll
                for (int j = 0; j < TN; j++)
                    acc[i][j] += regM[i] * regN[j];
        }
        __syncthreads();
    }

    #pragma unroll
    for (int i = 0; i < TM; i++) {
        int row = by * BM + threadRow * TM + i;
        #pragma unroll
        for (int j = 0; j < TN; j += 4) {
            int col = bx * BN + threadCol * TN + j;
            float4 o;
            o.x = acc[i][j + 0] + bias[col + 0];
            o.y = acc[i][j + 1] + bias[col + 1];
            o.z = acc[i][j + 2] + bias[col + 2];
            o.w = acc[i][j + 3] + bias[col + 3];
            *(float4*)(C + (size_t)row * Nd + col) = o;
        }
    }
}

// ---------------------------------------------------------------------------
// Landmarks: q_land (scaled by 1/sqrt(hd)=0.125) and k_land, mean over l=32.
// ---------------------------------------------------------------------------
__global__ void landmarks_kernel() {
    int bh = blockIdx.x;
    int b = bh / HH, h = bh % HH;
    for (int idx = threadIdx.x; idx < MM * HD; idx += blockDim.x) {
        int m = idx / HD, d = idx % HD;
        float sq = 0.f, sk = 0.f;
        size_t base = ((size_t)(b * TT + m * LL)) * (3 * EE);
        for (int g = 0; g < LL; g++) {
            const float* row = g_qkv + base + (size_t)g * 3 * EE;
            sq += row[h * HD + d];
            sk += row[EE + h * HD + d];
        }
        g_qland[(bh * MM + m) * HD + d] = sq * (1.0f / LL) * 0.125f;
        g_kland[(bh * MM + m) * HD + d] = sk * (1.0f / LL);
    }
}

// ---------------------------------------------------------------------------
// A = softmax(tril-mask(q_land @ k_land^T)); also per-bh max col-sum / row-sum.
// ---------------------------------------------------------------------------
__global__ void A_kernel() {
    int bh = blockIdx.x;
    __shared__ float kt[64 * 64];   // swizzled kl^T: (j,d) -> kt[d*64 + ((j+d)&63)]
    __shared__ float S[64 * 64];
    __shared__ float cbuf[64], rbuf[64];
    int tid = threadIdx.x;   // 256

    for (int idx = tid; idx < 4096; idx += 256) {
        int j = idx >> 6, d = idx & 63;
        kt[d * 64 + ((j + d) & 63)] = g_kland[bh * 4096 + j * 64 + d];
    }
    __syncthreads();

    const float* ql = g_qland + bh * 4096;
    for (int idx = tid; idx < 4096; idx += 256) {
        int i = idx >> 6, j = idx & 63;
        if (j <= i) {
            float s = 0.f;
            #pragma unroll 8
            for (int d = 0; d < 64; d++) s += ql[i * 64 + d] * kt[d * 64 + ((j + d) & 63)];
            S[idx] = s;
        } else {
            S[idx] = -INFINITY;
        }
    }
    __syncthreads();

    int w = tid / 32, lane = tid % 32;
    for (int r = 0; r < 8; r++) {
        int i = w * 8 + r;
        float v0 = S[i * 64 + lane], v1 = S[i * 64 + lane + 32];
        float mx = fmaxf(v0, v1);
        for (int o = 16; o > 0; o >>= 1) mx = fmaxf(mx, __shfl_xor_sync(0xffffffffu, mx, o));
        float e0 = expf(v0 - mx), e1 = expf(v1 - mx);
        float sm = e0 + e1;
        for (int o = 16; o > 0; o >>= 1) sm += __shfl_xor_sync(0xffffffffu, sm, o);
        float inv = 1.0f / sm;
        S[i * 64 + lane] = e0 * inv;
        S[i * 64 + lane + 32] = e1 * inv;
    }
    __syncthreads();

    for (int idx = tid; idx < 4096; idx += 256) g_A[bh * 4096 + idx] = S[idx];

    if (tid < 64) {
        float cs = 0.f, rs = 0.f;
        for (int i = 0; i < 64; i++) { cs += S[i * 64 + tid]; rs += S[tid * 64 + i]; }
        cbuf[tid] = cs; rbuf[tid] = rs;
    }
    __syncthreads();
    if (tid == 0) {
        float cm = cbuf[0], rm = rbuf[0];
        for (int i = 1; i < 64; i++) { cm = fmaxf(cm, cbuf[i]); rm = fmaxf(rm, rbuf[i]); }
        g_sums[bh * 2 + 0] = cm;   // max column-sum ("row" in ref naming)
        g_sums[bh * 2 + 1] = rm;   // max row-sum ("col" in ref naming)
    }
}

// ---------------------------------------------------------------------------
// 64x64 matmul helper: C = A @ B, 1024 threads. A reads broadcast (warp-uniform
// row), B reads lane-consecutive columns (conflict-free), writes coalesced.
// Works for generic (global or shared) pointers.
// ---------------------------------------------------------------------------
__device__ __forceinline__ void mm64(float* C, const float* A, const float* Bm) {
    int tid = threadIdx.x;
    int j = tid & 63;
    int i0 = tid >> 6;       // 0..15
    #pragma unroll
    for (int r = 0; r < 4; r++) {
        int i = i0 + 16 * r;
        float acc = 0.f;
        #pragma unroll 8
        for (int k = 0; k < 64; k++) acc += A[i * 64 + k] * Bm[k * 64 + j];
        C[i * 64 + j] = acc;
    }
}

// ---------------------------------------------------------------------------
// Moore-Penrose iterative pinv, 6 iterations, per (b,h). 1024 threads.
// z0 = A^T / (global_max_rowsum * global_max_colsum)
// ---------------------------------------------------------------------------
__global__ __launch_bounds__(1024)
void pinv_kernel() {
    int bh = blockIdx.x;
    __shared__ float Zs[4096];
    __shared__ float Ts[4096];
    int tid = threadIdx.x;

    float cm = 0.f, rm = 0.f;
    for (int i = 0; i < BH; i++) {
        cm = fmaxf(cm, g_sums[2 * i + 0]);
        rm = fmaxf(rm, g_sums[2 * i + 1]);
    }
    float inv = 1.0f / (cm * rm);

    const float* Ag = g_A + bh * 4096;
    float* XZ = g_XZ + bh * 4096;
    float* GT = g_T1 + bh * 4096;

    for (int idx = tid; idx < 4096; idx += 1024) {
        int i = idx >> 6, j = idx & 63;
        Zs[idx] = Ag[j * 64 + i] * inv;   // transpose
    }
    __syncthreads();

    for (int it = 0; it < 6; it++) {
        mm64(XZ, Ag, Zs); __syncthreads();
        for (int idx = tid; idx < 4096; idx += 1024)
            Ts[idx] = (((idx >> 6) == (idx & 63)) ? 7.0f : 0.0f) - XZ[idx];
        __syncthreads();
        mm64(GT, XZ, Ts); __syncthreads();
        for (int idx = tid; idx < 4096; idx += 1024)
            Ts[idx] = (((idx >> 6) == (idx & 63)) ? 15.0f : 0.0f) - GT[idx];
        __syncthreads();
        mm64(GT, XZ, Ts); __syncthreads();
        for (int idx = tid; idx < 4096; idx += 1024)
            Ts[idx] = (((idx >> 6) == (idx & 63)) ? 13.0f : 0.0f) - GT[idx];
        __syncthreads();
        mm64(GT, Zs, Ts); __syncthreads();
        for (int idx = tid; idx < 4096; idx += 1024) Zs[idx] = 0.25f * GT[idx];
        __syncthreads();
    }

    for (int idx = tid; idx < 4096; idx += 1024) g_z[bh * 4096 + idx] = Zs[idx];
}

// ---------------------------------------------------------------------------
// Bv + zB: B_t (tril over M x T) is nonzero only in its first 64 columns.
// Compute P = softmax(mask(q_land @ k[:64]^T)), Bv = P @ v[:64], zB = z @ Bv.
// ---------------------------------------------------------------------------
__global__ void Bv_kernel() {
    int bh = blockIdx.x;
    int b = bh / HH, h = bh % HH;
    __shared__ float kt[64 * 64];   // swizzled k^T, later reused as plain v
    __shared__ float S[64 * 64];
    __shared__ float B3[64 * 64];
    int tid = threadIdx.x;   // 256

    // load k for first 64 tokens (swizzled transpose)
    for (int idx = tid; idx < 4096; idx += 256) {
        int j = idx >> 6, d = idx & 63;
        kt[d * 64 + ((j + d) & 63)] = g_qkv[((size_t)(b * TT + j)) * 3 * EE + EE + h * HD + d];
    }
    __syncthreads();

    const float* ql = g_qland + bh * 4096;   // already scaled
    for (int idx = tid; idx < 4096; idx += 256) {
        int i = idx >> 6, j = idx & 63;
        if (j <= i) {
            float s = 0.f;
            #pragma unroll 8
            for (int d = 0; d < 64; d++) s += ql[i * 64 + d] * kt[d * 64 + ((j + d) & 63)];
            S[idx] = s;
        } else {
            S[idx] = -INFINITY;
        }
    }
    __syncthreads();

    int w = tid / 32, lane = tid % 32;
    for (int r = 0; r < 8; r++) {
        int i = w * 8 + r;
        float v0 = S[i * 64 + lane], v1 = S[i * 64 + lane + 32];
        float mx = fmaxf(v0, v1);
        for (int o = 16; o > 0; o >>= 1) mx = fmaxf(mx, __shfl_xor_sync(0xffffffffu, mx, o));
        float e0 = expf(v0 - mx), e1 = expf(v1 - mx);
        float sm = e0 + e1;
        for (int o = 16; o > 0; o >>= 1) sm += __shfl_xor_sync(0xffffffffu, sm, o);
        float inv = 1.0f / sm;
        S[i * 64 + lane] = e0 * inv;
        S[i * 64 + lane + 32] = e1 * inv;
    }
    __syncthreads();

    // load v for first 64 tokens (plain layout) over kt
    for (int idx = tid; idx < 4096; idx += 256) {
        int j = idx >> 6, d = idx & 63;
        kt[j * 64 + d] = g_qkv[((size_t)(b * TT + j)) * 3 * EE + 2 * EE + h * HD + d];
    }
    __syncthreads();

    // B3 = S @ v
    for (int idx = tid; idx < 4096; idx += 256) {
        int i = idx >> 6, d = idx & 63;
        float s = 0.f;
        #pragma unroll 8
        for (int k = 0; k < 64; k++) s += S[i * 64 + k] * kt[k * 64 + d];
        B3[idx] = s;
    }
    __syncthreads();

    // S = z @ B3  (zB)
    const float* z = g_z + bh * 4096;
    for (int idx = tid; idx < 4096; idx += 256) {
        int i = idx >> 6, d = idx & 63;
        float s = 0.f;
        #pragma unroll 8
        for (int k = 0; k < 64; k++) s += z[i * 64 + k] * B3[k * 64 + d];
        S[idx] = s;
    }
    __syncthreads();
    for (int idx = tid; idx < 4096; idx += 256) g_zB[bh * 4096 + idx] = S[idx];
}

// ---------------------------------------------------------------------------
// F = softmax(mask(q @ k_land^T)) : [BH, T, M]. Grid (T/64, BH), 256 threads.
// ---------------------------------------------------------------------------
__global__ void F_kernel() {
    int tt = blockIdx.x, bh = blockIdx.y;
    int b = bh / HH, h = bh % HH;
    __shared__ float kt[64 * 64];   // swizzled k_land^T
    __shared__ float qs[64 * 64];
    int tid = threadIdx.x;

    for (int idx = tid; idx < 4096; idx += 256) {
        int j = idx >> 6, d = idx & 63;
        kt[d * 64 + ((j + d) & 63)] = g_kland[bh * 4096 + j * 64 + d];
    }
    for (int idx = tid; idx < 4096; idx += 256) {
        int r = idx >> 6, d = idx & 63;
        qs[idx] = g_qkv[((size_t)(b * TT + tt * 64 + r)) * 3 * EE + h * HD + d] * 0.125f;
    }
    __syncthreads();

    int w = tid / 32, lane = tid % 32;
    for (int r = 0; r < 8; r++) {
        int row = w * 8 + r;
        int t = tt * 64 + row;
        float a0 = 0.f, a1 = 0.f;
        #pragma unroll 8
        for (int d = 0; d < 64; d++) {
            float qv = qs[row * 64 + d];
            a0 += qv * kt[d * 64 + ((lane + d) & 63)];
            a1 += qv * kt[d * 64 + ((lane + 32 + d) & 63)];
        }
        if (lane > t) a0 = -INFINITY;
        if (lane + 32 > t) a1 = -INFINITY;
        float mx = fmaxf(a0, a1);
        for (int o = 16; o > 0; o >>= 1) mx = fmaxf(mx, __shfl_xor_sync(0xffffffffu, mx, o));
        float e0 = expf(a0 - mx), e1 = expf(a1 - mx);
        float sm = e0 + e1;
        for (int o = 16; o > 0; o >>= 1) sm += __shfl_xor_sync(0xffffffffu, sm, o);
        float inv = 1.0f / sm;
        g_F[((size_t)bh * TT + t) * 64 + lane] = e0 * inv;
        g_F[((size_t)bh * TT + t) * 64 + lane + 32] = e1 * inv;
    }
}

// ---------------------------------------------------------------------------
// y[b,t,h*64+d] = sum_m F[bh,t,m] * zB[bh,m,d]. Grid (T/64, BH), 256 threads.
// ---------------------------------------------------------------------------
__global__ void Y_kernel() {
    int tt = blockIdx.x, bh = blockIdx.y;
    int b = bh / HH, h = bh % HH;
    __shared__ float zBs[64 * 64];
    __shared__ float Fs[64 * 64];
    int tid = threadIdx.x;

    for (int idx = tid; idx < 4096; idx += 256) zBs[idx] = g_zB[bh * 4096 + idx];
    for (int idx = tid; idx < 4096; idx += 256) {
        int r = idx >> 6, m = idx & 63;
        Fs[idx] = g_F[((size_t)bh * TT + tt * 64 + r) * 64 + m];
    }
    __syncthreads();

    int w = tid / 32, lane = tid % 32;
    for (int r = 0; r < 8; r++) {
        int row = w * 8 + r;
        int t = tt * 64 + row;
        float a0 = 0.f, a1 = 0.f;
        #pragma unroll 8
        for (int m = 0; m < 64; m++) {
            float fv = Fs[row * 64 + m];
            a0 += fv * zBs[m * 64 + lane];
            a1 += fv * zBs[m * 64 + lane + 32];
        }
        g_y[((size_t)(b * TT + t)) * EE + h * 64 + lane] = a0;
        g_y[((size_t)(b * TT + t)) * EE + h * 64 + lane + 32] = a1;
    }
}

// ---------------------------------------------------------------------------
extern "C" void kernel_launch(void* const* d_in, const int* in_sizes, int n_in,
                              void* d_out, int out_size) {
    const float* x      = (const float*)d_in[0];
    const float* w_qkv  = (const float*)d_in[1];
    const float* b_qkv  = (const float*)d_in[2];
    const float* w_proj = (const float*)d_in[3];
    const float* b_proj = (const float*)d_in[4];
    float* out = (float*)d_out;

    // 1. qkv = x @ w_qkv + b_qkv  -> g_qkv
    sgemm_bias<0><<<dim3(3 * EE / 128, BB * TT / 128), 256>>>(
        x, w_qkv, b_qkv, nullptr, BB * TT, 3 * EE, EE);
    // 2. landmarks (q scaled)
    landmarks_kernel<<<BH, 256>>>();
    // 3. A = softmax(masked ql@kl^T), per-bh sum maxima
    A_kernel<<<BH, 256>>>();
    // 4. pinv iterations -> g_z
    pinv_kernel<<<BH, 1024>>>();
    // 5. Bv = softmax(masked ql@k^T) @ v (first 64 cols only), zB = z @ Bv
    Bv_kernel<<<BH, 256>>>();
    // 6. F = softmax(masked q@kl^T)
    F_kernel<<<dim3(TT / 64, BH), 256>>>();
    // 7. y = F @ zB
    Y_kernel<<<dim3(TT / 64, BH), 256>>>();
    // 8. out = y @ w_proj + b_proj
    sgemm_bias<1><<<dim3(EE / 128, BB * TT / 128), 256>>>(
        nullptr, w_proj, b_proj, out, BB * TT, EE, EE);
}

// round 2
// speedup vs baseline: 1.2348x; 1.2348x over previous
#include <cuda_runtime.h>
#include <cuda_bf16.h>
#include <math.h>

// Problem constants
#define BB 2
#define TT 2048
#define EE 512
#define HH 8
#define HD 64
#define MM 64
#define LL 32
#define BH (BB*HH)

// Scratch (device globals; no runtime allocation)
__device__ float g_qkv[BB*TT*3*EE];      // 24 MB
__device__ float g_qland[BH*MM*HD];
__device__ float g_kland[BH*MM*HD];
__device__ float g_A[BH*MM*MM];
__device__ float g_z[BH*MM*MM];
__device__ float g_sums[BH*2];           // [colsum_max, rowsum_max] per bh
__device__ float g_zB[BH*MM*HD];
__device__ float g_F[BH*TT*MM];          // 8 MB
__device__ float g_y[BB*TT*EE];          // 8 MB

// ---------------------------------------------------------------------------
// SGEMM with bias: C[M,N] = A[M,K] @ B[K,N] + bias[N]
// DST==0: write g_qkv, read A param. DST==1: read g_y, write C param.
// BM=BN=128, BK=8, TM=TN=8, 256 threads.
// ---------------------------------------------------------------------------
template<int DST>
__global__ __launch_bounds__(256)
void sgemm_bias(const float* __restrict__ Ain, const float* __restrict__ Bm,
                const float* __restrict__ bias, float* __restrict__ Cout,
                int Md, int Nd, int Kd) {
    const int BM = 128, BN = 128, BK = 8, TM = 8, TN = 8;
    __shared__ float As[BK*BM];
    __shared__ float Bs[BK*BN];

    const float* A = (DST == 0) ? Ain : g_y;
    float* C = (DST == 0) ? g_qkv : Cout;

    int bx = blockIdx.x;   // N tile
    int by = blockIdx.y;   // M tile
    int tid = threadIdx.x;

    int threadRow = tid / (BN / TN);  // 0..15
    int threadCol = tid % (BN / TN);  // 0..15

    const float* Aptr = A + (size_t)by * BM * Kd;
    const float* Bptr = Bm + (size_t)bx * BN;

    int innerRowA = tid / (BK / 4);   // 0..127
    int innerColA = tid % (BK / 4);   // 0..1
    int innerRowB = tid / (BN / 4);   // 0..7
    int innerColB = tid % (BN / 4);   // 0..31

    float acc[TM][TN];
    #pragma unroll
    for (int i = 0; i < TM; i++)
        #pragma unroll
        for (int j = 0; j < TN; j++) acc[i][j] = 0.0f;

    for (int k0 = 0; k0 < Kd; k0 += BK) {
        float4 a4 = *(const float4*)(Aptr + (size_t)innerRowA * Kd + k0 + innerColA * 4);
        As[(innerColA * 4 + 0) * BM + innerRowA] = a4.x;
        As[(innerColA * 4 + 1) * BM + innerRowA] = a4.y;
        As[(innerColA * 4 + 2) * BM + innerRowA] = a4.z;
        As[(innerColA * 4 + 3) * BM + innerRowA] = a4.w;
        float4 b4 = *(const float4*)(Bptr + (size_t)(k0 + innerRowB) * Nd + innerColB * 4);
        *(float4*)(Bs + innerRowB * BN + innerColB * 4) = b4;
        __syncthreads();

        #pragma unroll
        for (int k = 0; k < BK; k++) {
            float regM[TM], regN[TN];
            #pragma unroll
            for (int i = 0; i < TM; i++) regM[i] = As[k * BM + threadRow * TM + i];
            #pragma unroll
            for (int j = 0; j < TN; j++) regN[j] = Bs[k * BN + threadCol * TN + j];
            #pragma unroll
            for (int i = 0; i < TM; i++)
                #pragma unroll
                for (int j = 0; j < TN; j++)
                    acc[i][j] += regM[i] * regN[j];
        }
        __syncthreads();
    }

    #pragma unroll
    for (int i = 0; i < TM; i++) {
        int row = by * BM + threadRow * TM + i;
        #pragma unroll
        for (int j = 0; j < TN; j += 4) {
            int col = bx * BN + threadCol * TN + j;
            float4 o;
            o.x = acc[i][j + 0] + bias[col + 0];
            o.y = acc[i][j + 1] + bias[col + 1];
            o.z = acc[i][j + 2] + bias[col + 2];
            o.w = acc[i][j + 3] + bias[col + 3];
            *(float4*)(C + (size_t)row * Nd + col) = o;
        }
    }
}

// ---------------------------------------------------------------------------
// Landmarks: q_land (scaled by 1/sqrt(hd)=0.125) and k_land, mean over l=32.
// ---------------------------------------------------------------------------
__global__ void landmarks_kernel() {
    int bh = blockIdx.x;
    int b = bh / HH, h = bh % HH;
    for (int idx = threadIdx.x; idx < MM * HD; idx += blockDim.x) {
        int m = idx / HD, d = idx % HD;
        float sq = 0.f, sk = 0.f;
        size_t base = ((size_t)(b * TT + m * LL)) * (3 * EE);
        for (int g = 0; g < LL; g++) {
            const float* row = g_qkv + base + (size_t)g * 3 * EE;
            sq += row[h * HD + d];
            sk += row[EE + h * HD + d];
        }
        g_qland[(bh * MM + m) * HD + d] = sq * (1.0f / LL) * 0.125f;
        g_kland[(bh * MM + m) * HD + d] = sk * (1.0f / LL);
    }
}

// ---------------------------------------------------------------------------
// A = softmax(tril-mask(q_land @ k_land^T)); also per-bh max col-sum / row-sum.
// ---------------------------------------------------------------------------
__global__ void A_kernel() {
    int bh = blockIdx.x;
    __shared__ float kt[64 * 64];   // swizzled kl^T: (j,d) -> kt[d*64 + ((j+d)&63)]
    __shared__ float S[64 * 64];
    __shared__ float cbuf[64], rbuf[64];
    int tid = threadIdx.x;   // 256

    for (int idx = tid; idx < 4096; idx += 256) {
        int j = idx >> 6, d = idx & 63;
        kt[d * 64 + ((j + d) & 63)] = g_kland[bh * 4096 + j * 64 + d];
    }
    __syncthreads();

    const float* ql = g_qland + bh * 4096;
    for (int idx = tid; idx < 4096; idx += 256) {
        int i = idx >> 6, j = idx & 63;
        if (j <= i) {
            float s = 0.f;
            #pragma unroll 8
            for (int d = 0; d < 64; d++) s += ql[i * 64 + d] * kt[d * 64 + ((j + d) & 63)];
            S[idx] = s;
        } else {
            S[idx] = -INFINITY;
        }
    }
    __syncthreads();

    int w = tid / 32, lane = tid % 32;
    for (int r = 0; r < 8; r++) {
        int i = w * 8 + r;
        float v0 = S[i * 64 + lane], v1 = S[i * 64 + lane + 32];
        float mx = fmaxf(v0, v1);
        for (int o = 16; o > 0; o >>= 1) mx = fmaxf(mx, __shfl_xor_sync(0xffffffffu, mx, o));
        float e0 = expf(v0 - mx), e1 = expf(v1 - mx);
        float sm = e0 + e1;
        for (int o = 16; o > 0; o >>= 1) sm += __shfl_xor_sync(0xffffffffu, sm, o);
        float inv = 1.0f / sm;
        S[i * 64 + lane] = e0 * inv;
        S[i * 64 + lane + 32] = e1 * inv;
    }
    __syncthreads();

    for (int idx = tid; idx < 4096; idx += 256) g_A[bh * 4096 + idx] = S[idx];

    if (tid < 64) {
        float cs = 0.f, rs = 0.f;
        for (int i = 0; i < 64; i++) { cs += S[i * 64 + tid]; rs += S[tid * 64 + i]; }
        cbuf[tid] = cs; rbuf[tid] = rs;
    }
    __syncthreads();
    if (tid == 0) {
        float cm = cbuf[0], rm = rbuf[0];
        for (int i = 1; i < 64; i++) { cm = fmaxf(cm, cbuf[i]); rm = fmaxf(rm, rbuf[i]); }
        g_sums[bh * 2 + 0] = cm;   // max column-sum ("row" in ref naming)
        g_sums[bh * 2 + 1] = rm;   // max row-sum ("col" in ref naming)
    }
}

// ---------------------------------------------------------------------------
// Register-tiled 64x64 matmul in shared memory (256 threads, 4x4 per thread).
// C = scale * L @ R'   where R' = (NEG ? dc*I - R : R).
// A-side loads are warp-broadcast float4; B-side float4 conflict-free.
// Ends with __syncthreads() so result is visible to the whole block.
// ---------------------------------------------------------------------------
template<bool NEG>
__device__ __forceinline__ void mm64t(float* __restrict__ C,
                                      const float* __restrict__ L,
                                      const float* __restrict__ R,
                                      float dc, float scale) {
    const int tx = threadIdx.x & 15;
    const int ty = threadIdx.x >> 4;
    const int i0 = ty * 4, j0 = tx * 4;

    float acc[4][4];
    #pragma unroll
    for (int r = 0; r < 4; r++)
        #pragma unroll
        for (int c = 0; c < 4; c++) acc[r][c] = 0.f;

    #pragma unroll
    for (int k4 = 0; k4 < 64; k4 += 4) {
        float4 a[4];
        #pragma unroll
        for (int r = 0; r < 4; r++)
            a[r] = *(const float4*)(L + (i0 + r) * 64 + k4);

        float4 b[4];
        #pragma unroll
        for (int kk = 0; kk < 4; kk++) {
            int k = k4 + kk;
            float4 bv = *(const float4*)(R + k * 64 + j0);
            if (NEG) {
                bv.x = -bv.x; bv.y = -bv.y; bv.z = -bv.z; bv.w = -bv.w;
                unsigned dj = (unsigned)(k - j0);
                if (dj < 4u) (&bv.x)[dj] += dc;
            }
            b[kk] = bv;
        }

        #pragma unroll
        for (int r = 0; r < 4; r++) {
            const float* ar = &a[r].x;
            #pragma unroll
            for (int kk = 0; kk < 4; kk++) {
                float av = ar[kk];
                acc[r][0] += av * b[kk].x;
                acc[r][1] += av * b[kk].y;
                acc[r][2] += av * b[kk].z;
                acc[r][3] += av * b[kk].w;
            }
        }
    }

    #pragma unroll
    for (int r = 0; r < 4; r++) {
        float4 o;
        o.x = acc[r][0] * scale;
        o.y = acc[r][1] * scale;
        o.z = acc[r][2] * scale;
        o.w = acc[r][3] * scale;
        *(float4*)(C + (i0 + r) * 64 + j0) = o;
    }
    __syncthreads();
}

// ---------------------------------------------------------------------------
// Moore-Penrose iterative pinv, 6 iterations, per (b,h). 256 threads.
// Fully shared-memory resident: A + 4 work buffers (80KB dynamic smem).
// Elementwise (c*I - X) fused into the B-operand read of each matmul.
//   xz = A @ z
//   t1 = xz @ (7I - xz)
//   t2 = xz @ (15I - t1)
//   z' = 0.25 * z @ (13I - t2)
// ---------------------------------------------------------------------------
__global__ __launch_bounds__(256)
void pinv_kernel() {
    extern __shared__ float sm[];
    float* As = sm;             // A (constant through iterations)
    float* W0 = sm + 4096;      // z   (initially)
    float* W1 = sm + 8192;      // xz / z-new (swaps with W0)
    float* W2 = sm + 12288;     // t1
    float* W3 = sm + 16384;     // t2

    int bh = blockIdx.x;
    int tid = threadIdx.x;

    // global max col-sum / row-sum across all bh
    float cm = 0.f, rm = 0.f;
    #pragma unroll
    for (int i = 0; i < BH; i++) {
        cm = fmaxf(cm, g_sums[2 * i + 0]);
        rm = fmaxf(rm, g_sums[2 * i + 1]);
    }
    float inv = 1.0f / (cm * rm);

    const float* Ag = g_A + bh * 4096;
    for (int idx = tid; idx < 4096; idx += 256) As[idx] = Ag[idx];
    __syncthreads();
    // z0 = A^T * inv
    for (int idx = tid; idx < 4096; idx += 256) {
        int i = idx >> 6, j = idx & 63;
        W0[idx] = As[j * 64 + i] * inv;
    }
    __syncthreads();

    float* z = W0;
    float* x = W1;
    for (int it = 0; it < 6; it++) {
        mm64t<false>(x,  As, z,  0.f,  1.0f);   // xz = A @ z
        mm64t<true >(W2, x,  x,  7.f,  1.0f);   // t1 = xz @ (7I - xz)
        mm64t<true >(W3, x,  W2, 15.f, 1.0f);   // t2 = xz @ (15I - t1)
        mm64t<true >(x,  z,  W3, 13.f, 0.25f);  // z' = 0.25 z @ (13I - t2)
        float* tmp = z; z = x; x = tmp;         // swap
    }

    for (int idx = tid; idx < 4096; idx += 256) g_z[bh * 4096 + idx] = z[idx];
}

// ---------------------------------------------------------------------------
// Bv + zB: B_t (tril over M x T) is nonzero only in its first 64 columns.
// Compute P = softmax(mask(q_land @ k[:64]^T)), Bv = P @ v[:64], zB = z @ Bv.
// ---------------------------------------------------------------------------
__global__ void Bv_kernel() {
    int bh = blockIdx.x;
    int b = bh / HH, h = bh % HH;
    __shared__ float kt[64 * 64];   // swizzled k^T, later reused as plain v
    __shared__ float S[64 * 64];
    __shared__ float B3[64 * 64];
    int tid = threadIdx.x;   // 256

    // load k for first 64 tokens (swizzled transpose)
    for (int idx = tid; idx < 4096; idx += 256) {
        int j = idx >> 6, d = idx & 63;
        kt[d * 64 + ((j + d) & 63)] = g_qkv[((size_t)(b * TT + j)) * 3 * EE + EE + h * HD + d];
    }
    __syncthreads();

    const float* ql = g_qland + bh * 4096;   // already scaled
    for (int idx = tid; idx < 4096; idx += 256) {
        int i = idx >> 6, j = idx & 63;
        if (j <= i) {
            float s = 0.f;
            #pragma unroll 8
            for (int d = 0; d < 64; d++) s += ql[i * 64 + d] * kt[d * 64 + ((j + d) & 63)];
            S[idx] = s;
        } else {
            S[idx] = -INFINITY;
        }
    }
    __syncthreads();

    int w = tid / 32, lane = tid % 32;
    for (int r = 0; r < 8; r++) {
        int i = w * 8 + r;
        float v0 = S[i * 64 + lane], v1 = S[i * 64 + lane + 32];
        float mx = fmaxf(v0, v1);
        for (int o = 16; o > 0; o >>= 1) mx = fmaxf(mx, __shfl_xor_sync(0xffffffffu, mx, o));
        float e0 = expf(v0 - mx), e1 = expf(v1 - mx);
        float sm = e0 + e1;
        for (int o = 16; o > 0; o >>= 1) sm += __shfl_xor_sync(0xffffffffu, sm, o);
        float inv = 1.0f / sm;
        S[i * 64 + lane] = e0 * inv;
        S[i * 64 + lane + 32] = e1 * inv;
    }
    __syncthreads();

    // load v for first 64 tokens (plain layout) over kt
    for (int idx = tid; idx < 4096; idx += 256) {
        int j = idx >> 6, d = idx & 63;
        kt[j * 64 + d] = g_qkv[((size_t)(b * TT + j)) * 3 * EE + 2 * EE + h * HD + d];
    }
    __syncthreads();

    // B3 = S @ v
    for (int idx = tid; idx < 4096; idx += 256) {
        int i = idx >> 6, d = idx & 63;
        float s = 0.f;
        #pragma unroll 8
        for (int k = 0; k < 64; k++) s += S[i * 64 + k] * kt[k * 64 + d];
        B3[idx] = s;
    }
    __syncthreads();

    // S = z @ B3  (zB)
    const float* z = g_z + bh * 4096;
    for (int idx = tid; idx < 4096; idx += 256) {
        int i = idx >> 6, d = idx & 63;
        float s = 0.f;
        #pragma unroll 8
        for (int k = 0; k < 64; k++) s += z[i * 64 + k] * B3[k * 64 + d];
        S[idx] = s;
    }
    __syncthreads();
    for (int idx = tid; idx < 4096; idx += 256) g_zB[bh * 4096 + idx] = S[idx];
}

// ---------------------------------------------------------------------------
// F = softmax(mask(q @ k_land^T)) : [BH, T, M]. Grid (T/64, BH), 256 threads.
// ---------------------------------------------------------------------------
__global__ void F_kernel() {
    int tt = blockIdx.x, bh = blockIdx.y;
    int b = bh / HH, h = bh % HH;
    __shared__ float kt[64 * 64];   // swizzled k_land^T
    __shared__ float qs[64 * 64];
    int tid = threadIdx.x;

    for (int idx = tid; idx < 4096; idx += 256) {
        int j = idx >> 6, d = idx & 63;
        kt[d * 64 + ((j + d) & 63)] = g_kland[bh * 4096 + j * 64 + d];
    }
    for (int idx = tid; idx < 4096; idx += 256) {
        int r = idx >> 6, d = idx & 63;
        qs[idx] = g_qkv[((size_t)(b * TT + tt * 64 + r)) * 3 * EE + h * HD + d] * 0.125f;
    }
    __syncthreads();

    int w = tid / 32, lane = tid % 32;
    for (int r = 0; r < 8; r++) {
        int row = w * 8 + r;
        int t = tt * 64 + row;
        float a0 = 0.f, a1 = 0.f;
        #pragma unroll 8
        for (int d = 0; d < 64; d++) {
            float qv = qs[row * 64 + d];
            a0 += qv * kt[d * 64 + ((lane + d) & 63)];
            a1 += qv * kt[d * 64 + ((lane + 32 + d) & 63)];
        }
        if (lane > t) a0 = -INFINITY;
        if (lane + 32 > t) a1 = -INFINITY;
        float mx = fmaxf(a0, a1);
        for (int o = 16; o > 0; o >>= 1) mx = fmaxf(mx, __shfl_xor_sync(0xffffffffu, mx, o));
        float e0 = expf(a0 - mx), e1 = expf(a1 - mx);
        float sm = e0 + e1;
        for (int o = 16; o > 0; o >>= 1) sm += __shfl_xor_sync(0xffffffffu, sm, o);
        float inv = 1.0f / sm;
        g_F[((size_t)bh * TT + t) * 64 + lane] = e0 * inv;
        g_F[((size_t)bh * TT + t) * 64 + lane + 32] = e1 * inv;
    }
}

// ---------------------------------------------------------------------------
// y[b,t,h*64+d] = sum_m F[bh,t,m] * zB[bh,m,d]. Grid (T/64, BH), 256 threads.
// ---------------------------------------------------------------------------
__global__ void Y_kernel() {
    int tt = blockIdx.x, bh = blockIdx.y;
    int b = bh / HH, h = bh % HH;
    __shared__ float zBs[64 * 64];
    __shared__ float Fs[64 * 64];
    int tid = threadIdx.x;

    for (int idx = tid; idx < 4096; idx += 256) zBs[idx] = g_zB[bh * 4096 + idx];
    for (int idx = tid; idx < 4096; idx += 256) {
        int r = idx >> 6, m = idx & 63;
        Fs[idx] = g_F[((size_t)bh * TT + tt * 64 + r) * 64 + m];
    }
    __syncthreads();

    int w = tid / 32, lane = tid % 32;
    for (int r = 0; r < 8; r++) {
        int row = w * 8 + r;
        int t = tt * 64 + row;
        float a0 = 0.f, a1 = 0.f;
        #pragma unroll 8
        for (int m = 0; m < 64; m++) {
            float fv = Fs[row * 64 + m];
            a0 += fv * zBs[m * 64 + lane];
            a1 += fv * zBs[m * 64 + lane + 32];
        }
        g_y[((size_t)(b * TT + t)) * EE + h * 64 + lane] = a0;
        g_y[((size_t)(b * TT + t)) * EE + h * 64 + lane + 32] = a1;
    }
}

// ---------------------------------------------------------------------------
extern "C" void kernel_launch(void* const* d_in, const int* in_sizes, int n_in,
                              void* d_out, int out_size) {
    const float* x      = (const float*)d_in[0];
    const float* w_qkv  = (const float*)d_in[1];
    const float* b_qkv  = (const float*)d_in[2];
    const float* w_proj = (const float*)d_in[3];
    const float* b_proj = (const float*)d_in[4];
    float* out = (float*)d_out;

    const int PINV_SMEM = 5 * 4096 * sizeof(float);   // 80 KB
    cudaFuncSetAttribute(pinv_kernel,
                         cudaFuncAttributeMaxDynamicSharedMemorySize, PINV_SMEM);

    // 1. qkv = x @ w_qkv + b_qkv  -> g_qkv
    sgemm_bias<0><<<dim3(3 * EE / 128, BB * TT / 128), 256>>>(
        x, w_qkv, b_qkv, nullptr, BB * TT, 3 * EE, EE);
    // 2. landmarks (q scaled)
    landmarks_kernel<<<BH, 256>>>();
    // 3. A = softmax(masked ql@kl^T), per-bh sum maxima
    A_kernel<<<BH, 256>>>();
    // 4. pinv iterations -> g_z
    pinv_kernel<<<BH, 256, PINV_SMEM>>>();
    // 5. Bv = softmax(masked ql@k^T) @ v (first 64 cols only), zB = z @ Bv
    Bv_kernel<<<BH, 256>>>();
    // 6. F = softmax(masked q@kl^T)
    F_kernel<<<dim3(TT / 64, BH), 256>>>();
    // 7. y = F @ zB
    Y_kernel<<<dim3(TT / 64, BH), 256>>>();
    // 8. out = y @ w_proj + b_proj
    sgemm_bias<1><<<dim3(EE / 128, BB * TT / 128), 256>>>(
        nullptr, w_proj, b_proj, out, BB * TT, EE, EE);
}

// round 4
// speedup vs baseline: 1.7870x; 1.4472x over previous
#include <cuda_runtime.h>
#include <cuda_bf16.h>
#include <math.h>
#include <stdint.h>

// Problem constants
#define BB 2
#define TT 2048
#define EE 512
#define HH 8
#define HD 64
#define MM 64
#define LL 32
#define BH (BB*HH)

// Scratch (device globals; no runtime allocation)
__device__ float g_qkv[BB*TT*3*EE];      // 24 MB
__device__ float g_qland[BH*MM*HD];
__device__ float g_kland[BH*MM*HD];
__device__ float g_A[BH*MM*MM];
__device__ float g_z[BH*MM*MM];
__device__ float g_sums[BH*2];
__device__ float g_zB[BH*MM*HD];
__device__ float g_F[BH*TT*MM];          // 8 MB
__device__ float g_y[BB*TT*EE];          // 8 MB
__device__ float g_wqkvT[3*EE*EE];       // transposed w_qkv [1536,512]
__device__ float g_wprojT[EE*EE];        // transposed w_proj [512,512]

__device__ __forceinline__ uint32_t tf32r(float x) {
    uint32_t r; asm("cvt.rna.tf32.f32 %0, %1;" : "=r"(r) : "f"(x)); return r;
}

__device__ __forceinline__ void mma_tf32(float* d, const uint32_t* a,
                                         const uint32_t* b, const float* c) {
    asm volatile(
        "mma.sync.aligned.m16n8k8.row.col.f32.tf32.tf32.f32 "
        "{%0,%1,%2,%3}, {%4,%5,%6,%7}, {%8,%9}, {%10,%11,%12,%13};"
        : "=f"(d[0]), "=f"(d[1]), "=f"(d[2]), "=f"(d[3])
        : "r"(a[0]), "r"(a[1]), "r"(a[2]), "r"(a[3]),
          "r"(b[0]), "r"(b[1]),
          "f"(c[0]), "f"(c[1]), "f"(c[2]), "f"(c[3]));
}

// ---------------------------------------------------------------------------
// Weight transpose: src[K,N] -> dst[N,K]
// ---------------------------------------------------------------------------
__global__ void transpose_kernel(const float* __restrict__ src, float* __restrict__ dst,
                                 int K, int N) {
    __shared__ float t[32][33];
    int bx = blockIdx.x * 32;   // N
    int by = blockIdx.y * 32;   // K
    int x = threadIdx.x;
    for (int y = threadIdx.y; y < 32; y += 8)
        t[y][x] = src[(size_t)(by + y) * N + bx + x];
    __syncthreads();
    for (int y = threadIdx.y; y < 32; y += 8)
        dst[(size_t)(bx + y) * K + by + x] = t[x][y];
}

// ---------------------------------------------------------------------------
// TF32 mma.sync GEMM: C[4096, Nd] = A[4096, 512] @ BT[Nd, 512]^T + bias
// MODE 0: A = x (param), BT = g_wqkvT, C = g_qkv
// MODE 1: A = g_y,       BT = g_wprojT, C = out (param)
// CTA tile 128x128, BK=32, 256 threads = 8 warps, warp tile 64x32
// (4x4 grid of m16n8k8). Smem rows padded to 36 floats (conflict-free frags).
// ---------------------------------------------------------------------------
#define GBK 32
#define GSTRIDE 36

template<int MODE>
__global__ __launch_bounds__(256)
void mma_gemm(const float* __restrict__ Ain, const float* __restrict__ bias,
              float* __restrict__ Cout, int Nd) {
    __shared__ float As[128 * GSTRIDE];
    __shared__ float Bs[128 * GSTRIDE];

    const float* A  = (MODE == 0) ? Ain : g_y;
    const float* BT = (MODE == 0) ? g_wqkvT : g_wprojT;
    float* C        = (MODE == 0) ? g_qkv : Cout;

    int tid = threadIdx.x, wid = tid >> 5, lane = tid & 31;
    int bx = blockIdx.x, by = blockIdx.y;
    int wm = (wid >> 2) * 64;     // warp m offset: 0 / 64
    int wn = (wid & 3) * 32;      // warp n offset: 0/32/64/96
    int grp = lane >> 2;          // 0..7
    int tig = lane & 3;           // 0..3

    const float* Abase = A  + (size_t)by * 128 * EE;
    const float* Bbase = BT + (size_t)bx * 128 * EE;

    float acc[4][4][4];
    #pragma unroll
    for (int mt = 0; mt < 4; mt++)
        #pragma unroll
        for (int nt = 0; nt < 4; nt++)
            #pragma unroll
            for (int r = 0; r < 4; r++) acc[mt][nt][r] = 0.f;

    for (int k0 = 0; k0 < EE; k0 += GBK) {
        // load 128x32 chunks of A and B^T; 256 threads x 4 float4 each
        #pragma unroll
        for (int i = 0; i < 4; i++) {
            int s = tid + i * 256;          // float4 slot 0..1023
            int r = s >> 3;                 // row 0..127
            int c4 = (s & 7) * 4;           // col 0..28

            float4 av = *(const float4*)(Abase + (size_t)r * EE + k0 + c4);
            As[r * GSTRIDE + c4 + 0] = __uint_as_float(tf32r(av.x));
            As[r * GSTRIDE + c4 + 1] = __uint_as_float(tf32r(av.y));
            As[r * GSTRIDE + c4 + 2] = __uint_as_float(tf32r(av.z));
            As[r * GSTRIDE + c4 + 3] = __uint_as_float(tf32r(av.w));

            float4 bv = *(const float4*)(Bbase + (size_t)r * EE + k0 + c4);
            Bs[r * GSTRIDE + c4 + 0] = __uint_as_float(tf32r(bv.x));
            Bs[r * GSTRIDE + c4 + 1] = __uint_as_float(tf32r(bv.y));
            Bs[r * GSTRIDE + c4 + 2] = __uint_as_float(tf32r(bv.z));
            Bs[r * GSTRIDE + c4 + 3] = __uint_as_float(tf32r(bv.w));
        }
        __syncthreads();

        #pragma unroll
        for (int kk = 0; kk < GBK; kk += 8) {
            uint32_t af[4][4], bf[4][2];
            #pragma unroll
            for (int mt = 0; mt < 4; mt++) {
                int m = wm + mt * 16;
                af[mt][0] = __float_as_uint(As[(m + grp) * GSTRIDE + kk + tig]);
                af[mt][1] = __float_as_uint(As[(m + grp + 8) * GSTRIDE + kk + tig]);
                af[mt][2] = __float_as_uint(As[(m + grp) * GSTRIDE + kk + tig + 4]);
                af[mt][3] = __float_as_uint(As[(m + grp + 8) * GSTRIDE + kk + tig + 4]);
            }
            #pragma unroll
            for (int nt = 0; nt < 4; nt++) {
                int n = wn + nt * 8;
                bf[nt][0] = __float_as_uint(Bs[(n + grp) * GSTRIDE + kk + tig]);
                bf[nt][1] = __float_as_uint(Bs[(n + grp) * GSTRIDE + kk + tig + 4]);
            }
            #pragma unroll
            for (int mt = 0; mt < 4; mt++)
                #pragma unroll
                for (int nt = 0; nt < 4; nt++)
                    mma_tf32(acc[mt][nt], af[mt], bf[nt], acc[mt][nt]);
        }
        __syncthreads();
    }

    // epilogue
    #pragma unroll
    for (int mt = 0; mt < 4; mt++) {
        int row0 = by * 128 + wm + mt * 16 + grp;
        #pragma unroll
        for (int nt = 0; nt < 4; nt++) {
            int col0 = bx * 128 + wn + nt * 8 + tig * 2;
            float b0 = bias[col0], b1 = bias[col0 + 1];
            float2 o0 = make_float2(acc[mt][nt][0] + b0, acc[mt][nt][1] + b1);
            float2 o1 = make_float2(acc[mt][nt][2] + b0, acc[mt][nt][3] + b1);
            *(float2*)(C + (size_t)row0 * Nd + col0) = o0;
            *(float2*)(C + (size_t)(row0 + 8) * Nd + col0) = o1;
        }
    }
}

// ---------------------------------------------------------------------------
// Landmarks: q_land (scaled by 1/sqrt(hd)=0.125) and k_land, mean over l=32.
// ---------------------------------------------------------------------------
__global__ void landmarks_kernel() {
    int bh = blockIdx.x;
    int b = bh / HH, h = bh % HH;
    for (int idx = threadIdx.x; idx < MM * HD; idx += blockDim.x) {
        int m = idx / HD, d = idx % HD;
        float sq = 0.f, sk = 0.f;
        size_t base = ((size_t)(b * TT + m * LL)) * (3 * EE);
        for (int g = 0; g < LL; g++) {
            const float* row = g_qkv + base + (size_t)g * 3 * EE;
            sq += row[h * HD + d];
            sk += row[EE + h * HD + d];
        }
        g_qland[(bh * MM + m) * HD + d] = sq * (1.0f / LL) * 0.125f;
        g_kland[(bh * MM + m) * HD + d] = sk * (1.0f / LL);
    }
}

// ---------------------------------------------------------------------------
// A = softmax(tril-mask(q_land @ k_land^T)); also per-bh max col-sum / row-sum.
// ---------------------------------------------------------------------------
__global__ void A_kernel() {
    int bh = blockIdx.x;
    __shared__ float kt[64 * 64];
    __shared__ float S[64 * 64];
    __shared__ float cbuf[64], rbuf[64];
    int tid = threadIdx.x;

    for (int idx = tid; idx < 4096; idx += 256) {
        int j = idx >> 6, d = idx & 63;
        kt[d * 64 + ((j + d) & 63)] = g_kland[bh * 4096 + j * 64 + d];
    }
    __syncthreads();

    const float* ql = g_qland + bh * 4096;
    for (int idx = tid; idx < 4096; idx += 256) {
        int i = idx >> 6, j = idx & 63;
        if (j <= i) {
            float s = 0.f;
            #pragma unroll 8
            for (int d = 0; d < 64; d++) s += ql[i * 64 + d] * kt[d * 64 + ((j + d) & 63)];
            S[idx] = s;
        } else {
            S[idx] = -INFINITY;
        }
    }
    __syncthreads();

    int w = tid / 32, lane = tid % 32;
    for (int r = 0; r < 8; r++) {
        int i = w * 8 + r;
        float v0 = S[i * 64 + lane], v1 = S[i * 64 + lane + 32];
        float mx = fmaxf(v0, v1);
        for (int o = 16; o > 0; o >>= 1) mx = fmaxf(mx, __shfl_xor_sync(0xffffffffu, mx, o));
        float e0 = expf(v0 - mx), e1 = expf(v1 - mx);
        float sm = e0 + e1;
        for (int o = 16; o > 0; o >>= 1) sm += __shfl_xor_sync(0xffffffffu, sm, o);
        float inv = 1.0f / sm;
        S[i * 64 + lane] = e0 * inv;
        S[i * 64 + lane + 32] = e1 * inv;
    }
    __syncthreads();

    for (int idx = tid; idx < 4096; idx += 256) g_A[bh * 4096 + idx] = S[idx];

    if (tid < 64) {
        float cs = 0.f, rs = 0.f;
        for (int i = 0; i < 64; i++) { cs += S[i * 64 + tid]; rs += S[tid * 64 + i]; }
        cbuf[tid] = cs; rbuf[tid] = rs;
    }
    __syncthreads();
    if (tid == 0) {
        float cm = cbuf[0], rm = rbuf[0];
        for (int i = 1; i < 64; i++) { cm = fmaxf(cm, cbuf[i]); rm = fmaxf(rm, rbuf[i]); }
        g_sums[bh * 2 + 0] = cm;
        g_sums[bh * 2 + 1] = rm;
    }
}

// ---------------------------------------------------------------------------
// Register-tiled 64x64 matmul in shared memory (256 threads, 4x4 per thread).
// C = scale * L @ R'   where R' = (NEG ? dc*I - R : R).
// ---------------------------------------------------------------------------
template<bool NEG>
__device__ __forceinline__ void mm64t(float* __restrict__ C,
                                      const float* __restrict__ L,
                                      const float* __restrict__ R,
                                      float dc, float scale) {
    const int tx = threadIdx.x & 15;
    const int ty = threadIdx.x >> 4;
    const int i0 = ty * 4, j0 = tx * 4;

    float acc[4][4];
    #pragma unroll
    for (int r = 0; r < 4; r++)
        #pragma unroll
        for (int c = 0; c < 4; c++) acc[r][c] = 0.f;

    #pragma unroll
    for (int k4 = 0; k4 < 64; k4 += 4) {
        float4 a[4];
        #pragma unroll
        for (int r = 0; r < 4; r++)
            a[r] = *(const float4*)(L + (i0 + r) * 64 + k4);

        float4 b[4];
        #pragma unroll
        for (int kk = 0; kk < 4; kk++) {
            int k = k4 + kk;
            float4 bv = *(const float4*)(R + k * 64 + j0);
            if (NEG) {
                bv.x = -bv.x; bv.y = -bv.y; bv.z = -bv.z; bv.w = -bv.w;
                unsigned dj = (unsigned)(k - j0);
                if (dj < 4u) (&bv.x)[dj] += dc;
            }
            b[kk] = bv;
        }

        #pragma unroll
        for (int r = 0; r < 4; r++) {
            const float* ar = &a[r].x;
            #pragma unroll
            for (int kk = 0; kk < 4; kk++) {
                float av = ar[kk];
                acc[r][0] += av * b[kk].x;
                acc[r][1] += av * b[kk].y;
                acc[r][2] += av * b[kk].z;
                acc[r][3] += av * b[kk].w;
            }
        }
    }

    #pragma unroll
    for (int r = 0; r < 4; r++) {
        float4 o;
        o.x = acc[r][0] * scale;
        o.y = acc[r][1] * scale;
        o.z = acc[r][2] * scale;
        o.w = acc[r][3] * scale;
        *(float4*)(C + (i0 + r) * 64 + j0) = o;
    }
    __syncthreads();
}

// ---------------------------------------------------------------------------
// Moore-Penrose iterative pinv, 6 iterations, per (b,h). 256 threads, 80KB smem.
// ---------------------------------------------------------------------------
__global__ __launch_bounds__(256)
void pinv_kernel() {
    extern __shared__ float sm[];
    float* As = sm;
    float* W0 = sm + 4096;
    float* W1 = sm + 8192;
    float* W2 = sm + 12288;
    float* W3 = sm + 16384;

    int bh = blockIdx.x;
    int tid = threadIdx.x;

    float cm = 0.f, rm = 0.f;
    #pragma unroll
    for (int i = 0; i < BH; i++) {
        cm = fmaxf(cm, g_sums[2 * i + 0]);
        rm = fmaxf(rm, g_sums[2 * i + 1]);
    }
    float inv = 1.0f / (cm * rm);

    const float* Ag = g_A + bh * 4096;
    for (int idx = tid; idx < 4096; idx += 256) As[idx] = Ag[idx];
    __syncthreads();
    for (int idx = tid; idx < 4096; idx += 256) {
        int i = idx >> 6, j = idx & 63;
        W0[idx] = As[j * 64 + i] * inv;
    }
    __syncthreads();

    float* z = W0;
    float* x = W1;
    for (int it = 0; it < 6; it++) {
        mm64t<false>(x,  As, z,  0.f,  1.0f);
        mm64t<true >(W2, x,  x,  7.f,  1.0f);
        mm64t<true >(W3, x,  W2, 15.f, 1.0f);
        mm64t<true >(x,  z,  W3, 13.f, 0.25f);
        float* tmp = z; z = x; x = tmp;
    }

    for (int idx = tid; idx < 4096; idx += 256) g_z[bh * 4096 + idx] = z[idx];
}

// ---------------------------------------------------------------------------
// Bv + zB: B_t nonzero only in first 64 columns.
// ---------------------------------------------------------------------------
__global__ void Bv_kernel() {
    int bh = blockIdx.x;
    int b = bh / HH, h = bh % HH;
    __shared__ float kt[64 * 64];
    __shared__ float S[64 * 64];
    __shared__ float B3[64 * 64];
    int tid = threadIdx.x;

    for (int idx = tid; idx < 4096; idx += 256) {
        int j = idx >> 6, d = idx & 63;
        kt[d * 64 + ((j + d) & 63)] = g_qkv[((size_t)(b * TT + j)) * 3 * EE + EE + h * HD + d];
    }
    __syncthreads();

    const float* ql = g_qland + bh * 4096;
    for (int idx = tid; idx < 4096; idx += 256) {
        int i = idx >> 6, j = idx & 63;
        if (j <= i) {
            float s = 0.f;
            #pragma unroll 8
            for (int d = 0; d < 64; d++) s += ql[i * 64 + d] * kt[d * 64 + ((j + d) & 63)];
            S[idx] = s;
        } else {
            S[idx] = -INFINITY;
        }
    }
    __syncthreads();

    int w = tid / 32, lane = tid % 32;
    for (int r = 0; r < 8; r++) {
        int i = w * 8 + r;
        float v0 = S[i * 64 + lane], v1 = S[i * 64 + lane + 32];
        float mx = fmaxf(v0, v1);
        for (int o = 16; o > 0; o >>= 1) mx = fmaxf(mx, __shfl_xor_sync(0xffffffffu, mx, o));
        float e0 = expf(v0 - mx), e1 = expf(v1 - mx);
        float sm = e0 + e1;
        for (int o = 16; o > 0; o >>= 1) sm += __shfl_xor_sync(0xffffffffu, sm, o);
        float inv = 1.0f / sm;
        S[i * 64 + lane] = e0 * inv;
        S[i * 64 + lane + 32] = e1 * inv;
    }
    __syncthreads();

    for (int idx = tid; idx < 4096; idx += 256) {
        int j = idx >> 6, d = idx & 63;
        kt[j * 64 + d] = g_qkv[((size_t)(b * TT + j)) * 3 * EE + 2 * EE + h * HD + d];
    }
    __syncthreads();

    for (int idx = tid; idx < 4096; idx += 256) {
        int i = idx >> 6, d = idx & 63;
        float s = 0.f;
        #pragma unroll 8
        for (int k = 0; k < 64; k++) s += S[i * 64 + k] * kt[k * 64 + d];
        B3[idx] = s;
    }
    __syncthreads();

    const float* z = g_z + bh * 4096;
    for (int idx = tid; idx < 4096; idx += 256) {
        int i = idx >> 6, d = idx & 63;
        float s = 0.f;
        #pragma unroll 8
        for (int k = 0; k < 64; k++) s += z[i * 64 + k] * B3[k * 64 + d];
        S[idx] = s;
    }
    __syncthreads();
    for (int idx = tid; idx < 4096; idx += 256) g_zB[bh * 4096 + idx] = S[idx];
}

// ---------------------------------------------------------------------------
// F = softmax(mask(q @ k_land^T)) : [BH, T, M].
// ---------------------------------------------------------------------------
__global__ void F_kernel() {
    int tt = blockIdx.x, bh = blockIdx.y;
    int b = bh / HH, h = bh % HH;
    __shared__ float kt[64 * 64];
    __shared__ float qs[64 * 64];
    int tid = threadIdx.x;

    for (int idx = tid; idx < 4096; idx += 256) {
        int j = idx >> 6, d = idx & 63;
        kt[d * 64 + ((j + d) & 63)] = g_kland[bh * 4096 + j * 64 + d];
    }
    for (int idx = tid; idx < 4096; idx += 256) {
        int r = idx >> 6, d = idx & 63;
        qs[idx] = g_qkv[((size_t)(b * TT + tt * 64 + r)) * 3 * EE + h * HD + d] * 0.125f;
    }
    __syncthreads();

    int w = tid / 32, lane = tid % 32;
    for (int r = 0; r < 8; r++) {
        int row = w * 8 + r;
        int t = tt * 64 + row;
        float a0 = 0.f, a1 = 0.f;
        #pragma unroll 8
        for (int d = 0; d < 64; d++) {
            float qv = qs[row * 64 + d];
            a0 += qv * kt[d * 64 + ((lane + d) & 63)];
            a1 += qv * kt[d * 64 + ((lane + 32 + d) & 63)];
        }
        if (lane > t) a0 = -INFINITY;
        if (lane + 32 > t) a1 = -INFINITY;
        float mx = fmaxf(a0, a1);
        for (int o = 16; o > 0; o >>= 1) mx = fmaxf(mx, __shfl_xor_sync(0xffffffffu, mx, o));
        float e0 = expf(a0 - mx), e1 = expf(a1 - mx);
        float sm = e0 + e1;
        for (int o = 16; o > 0; o >>= 1) sm += __shfl_xor_sync(0xffffffffu, sm, o);
        float inv = 1.0f / sm;
        g_F[((size_t)bh * TT + t) * 64 + lane] = e0 * inv;
        g_F[((size_t)bh * TT + t) * 64 + lane + 32] = e1 * inv;
    }
}

// ---------------------------------------------------------------------------
// y = F @ zB scattered into [B,T,E] layout.
// ---------------------------------------------------------------------------
__global__ void Y_kernel() {
    int tt = blockIdx.x, bh = blockIdx.y;
    int b = bh / HH, h = bh % HH;
    __shared__ float zBs[64 * 64];
    __shared__ float Fs[64 * 64];
    int tid = threadIdx.x;

    for (int idx = tid; idx < 4096; idx += 256) zBs[idx] = g_zB[bh * 4096 + idx];
    for (int idx = tid; idx < 4096; idx += 256) {
        int r = idx >> 6, m = idx & 63;
        Fs[idx] = g_F[((size_t)bh * TT + tt * 64 + r) * 64 + m];
    }
    __syncthreads();

    int w = tid / 32, lane = tid % 32;
    for (int r = 0; r < 8; r++) {
        int row = w * 8 + r;
        int t = tt * 64 + row;
        float a0 = 0.f, a1 = 0.f;
        #pragma unroll 8
        for (int m = 0; m < 64; m++) {
            float fv = Fs[row * 64 + m];
            a0 += fv * zBs[m * 64 + lane];
            a1 += fv * zBs[m * 64 + lane + 32];
        }
        g_y[((size_t)(b * TT + t)) * EE + h * 64 + lane] = a0;
        g_y[((size_t)(b * TT + t)) * EE + h * 64 + lane + 32] = a1;
    }
}

// ---------------------------------------------------------------------------
extern "C" void kernel_launch(void* const* d_in, const int* in_sizes, int n_in,
                              void* d_out, int out_size) {
    const float* x      = (const float*)d_in[0];
    const float* w_qkv  = (const float*)d_in[1];
    const float* b_qkv  = (const float*)d_in[2];
    const float* w_proj = (const float*)d_in[3];
    const float* b_proj = (const float*)d_in[4];
    float* out = (float*)d_out;

    const int PINV_SMEM = 5 * 4096 * sizeof(float);   // 80 KB
    cudaFuncSetAttribute(pinv_kernel,
                         cudaFuncAttributeMaxDynamicSharedMemorySize, PINV_SMEM);

    float* wqkvT;  cudaGetSymbolAddress((void**)&wqkvT,  g_wqkvT);
    float* wprojT; cudaGetSymbolAddress((void**)&wprojT, g_wprojT);

    // 0. transpose weights
    transpose_kernel<<<dim3(3 * EE / 32, EE / 32), dim3(32, 8)>>>(w_qkv, wqkvT, EE, 3 * EE);
    transpose_kernel<<<dim3(EE / 32, EE / 32), dim3(32, 8)>>>(w_proj, wprojT, EE, EE);

    // 1. qkv = x @ w_qkv + b_qkv  (tf32 mma.sync)
    mma_gemm<0><<<dim3(3 * EE / 128, BB * TT / 128), 256>>>(x, b_qkv, nullptr, 3 * EE);
    // 2. landmarks
    landmarks_kernel<<<BH, 256>>>();
    // 3. A softmax + sum maxima
    A_kernel<<<BH, 256>>>();
    // 4. pinv
    pinv_kernel<<<BH, 256, PINV_SMEM>>>();
    // 5. Bv / zB
    Bv_kernel<<<BH, 256>>>();
    // 6. F
    F_kernel<<<dim3(TT / 64, BH), 256>>>();
    // 7. y = F @ zB
    Y_kernel<<<dim3(TT / 64, BH), 256>>>();
    // 8. out = y @ w_proj + b_proj  (tf32 mma.sync)
    mma_gemm<1><<<dim3(EE / 128, BB * TT / 128), 256>>>(nullptr, b_proj, out, EE);
}

// round 5
// speedup vs baseline: 2.3855x; 1.3349x over previous
#include <cuda_runtime.h>
#include <cuda_bf16.h>
#include <math.h>
#include <stdint.h>

// Problem constants
#define BB 2
#define TT 2048
#define EE 512
#define HH 8
#define HD 64
#define MM 64
#define LL 32
#define BH (BB*HH)

// Scratch (device globals; no runtime allocation)
__device__ float g_qkv[BB*TT*3*EE];      // 24 MB
__device__ float g_qland[BH*MM*HD];
__device__ float g_kland[BH*MM*HD];
__device__ float g_A[BH*MM*MM];
__device__ float g_z[BH*MM*MM];
__device__ float g_sums[BH*2];
__device__ float g_zB[BH*MM*HD];
__device__ float g_y[BB*TT*EE];          // 8 MB
__device__ float g_wqkvT[3*EE*EE];       // transposed w_qkv [1536,512]
__device__ float g_wprojT[EE*EE];        // transposed w_proj [512,512]

__device__ __forceinline__ uint32_t tf32r(float x) {
    uint32_t r; asm("cvt.rna.tf32.f32 %0, %1;" : "=r"(r) : "f"(x)); return r;
}
__device__ __forceinline__ float tf32f(float x) {
    return __uint_as_float(tf32r(x));
}

__device__ __forceinline__ void mma_tf32(float* d, const uint32_t* a,
                                         const uint32_t* b, const float* c) {
    asm volatile(
        "mma.sync.aligned.m16n8k8.row.col.f32.tf32.tf32.f32 "
        "{%0,%1,%2,%3}, {%4,%5,%6,%7}, {%8,%9}, {%10,%11,%12,%13};"
        : "=f"(d[0]), "=f"(d[1]), "=f"(d[2]), "=f"(d[3])
        : "r"(a[0]), "r"(a[1]), "r"(a[2]), "r"(a[3]),
          "r"(b[0]), "r"(b[1]),
          "f"(c[0]), "f"(c[1]), "f"(c[2]), "f"(c[3]));
}

// ---------------------------------------------------------------------------
// Weight transpose: src[K,N] -> dst[N,K]
// ---------------------------------------------------------------------------
__global__ void transpose_kernel(const float* __restrict__ src, float* __restrict__ dst,
                                 int K, int N) {
    __shared__ float t[32][33];
    int bx = blockIdx.x * 32;   // N
    int by = blockIdx.y * 32;   // K
    int x = threadIdx.x;
    for (int y = threadIdx.y; y < 32; y += 8)
        t[y][x] = src[(size_t)(by + y) * N + bx + x];
    __syncthreads();
    for (int y = threadIdx.y; y < 32; y += 8)
        dst[(size_t)(bx + y) * K + by + x] = t[x][y];
}

// ---------------------------------------------------------------------------
// TF32 mma.sync GEMM: C[4096, Nd] = A[4096, 512] @ BT[Nd, 512]^T + bias
// MODE 0: A = x (param), BT = g_wqkvT, C = g_qkv
// MODE 1: A = g_y,       BT = g_wprojT, C = out (param)
// ---------------------------------------------------------------------------
#define GBK 32
#define GSTRIDE 36

template<int MODE>
__global__ __launch_bounds__(256)
void mma_gemm(const float* __restrict__ Ain, const float* __restrict__ bias,
              float* __restrict__ Cout, int Nd) {
    __shared__ float As[128 * GSTRIDE];
    __shared__ float Bs[128 * GSTRIDE];

    const float* A  = (MODE == 0) ? Ain : g_y;
    const float* BT = (MODE == 0) ? g_wqkvT : g_wprojT;
    float* C        = (MODE == 0) ? g_qkv : Cout;

    int tid = threadIdx.x, wid = tid >> 5, lane = tid & 31;
    int bx = blockIdx.x, by = blockIdx.y;
    int wm = (wid >> 2) * 64;
    int wn = (wid & 3) * 32;
    int grp = lane >> 2;
    int tig = lane & 3;

    const float* Abase = A  + (size_t)by * 128 * EE;
    const float* Bbase = BT + (size_t)bx * 128 * EE;

    float acc[4][4][4];
    #pragma unroll
    for (int mt = 0; mt < 4; mt++)
        #pragma unroll
        for (int nt = 0; nt < 4; nt++)
            #pragma unroll
            for (int r = 0; r < 4; r++) acc[mt][nt][r] = 0.f;

    for (int k0 = 0; k0 < EE; k0 += GBK) {
        #pragma unroll
        for (int i = 0; i < 4; i++) {
            int s = tid + i * 256;
            int r = s >> 3;
            int c4 = (s & 7) * 4;

            float4 av = *(const float4*)(Abase + (size_t)r * EE + k0 + c4);
            As[r * GSTRIDE + c4 + 0] = tf32f(av.x);
            As[r * GSTRIDE + c4 + 1] = tf32f(av.y);
            As[r * GSTRIDE + c4 + 2] = tf32f(av.z);
            As[r * GSTRIDE + c4 + 3] = tf32f(av.w);

            float4 bv = *(const float4*)(Bbase + (size_t)r * EE + k0 + c4);
            Bs[r * GSTRIDE + c4 + 0] = tf32f(bv.x);
            Bs[r * GSTRIDE + c4 + 1] = tf32f(bv.y);
            Bs[r * GSTRIDE + c4 + 2] = tf32f(bv.z);
            Bs[r * GSTRIDE + c4 + 3] = tf32f(bv.w);
        }
        __syncthreads();

        #pragma unroll
        for (int kk = 0; kk < GBK; kk += 8) {
            uint32_t af[4][4], bf[4][2];
            #pragma unroll
            for (int mt = 0; mt < 4; mt++) {
                int m = wm + mt * 16;
                af[mt][0] = __float_as_uint(As[(m + grp) * GSTRIDE + kk + tig]);
                af[mt][1] = __float_as_uint(As[(m + grp + 8) * GSTRIDE + kk + tig]);
                af[mt][2] = __float_as_uint(As[(m + grp) * GSTRIDE + kk + tig + 4]);
                af[mt][3] = __float_as_uint(As[(m + grp + 8) * GSTRIDE + kk + tig + 4]);
            }
            #pragma unroll
            for (int nt = 0; nt < 4; nt++) {
                int n = wn + nt * 8;
                bf[nt][0] = __float_as_uint(Bs[(n + grp) * GSTRIDE + kk + tig]);
                bf[nt][1] = __float_as_uint(Bs[(n + grp) * GSTRIDE + kk + tig + 4]);
            }
            #pragma unroll
            for (int mt = 0; mt < 4; mt++)
                #pragma unroll
                for (int nt = 0; nt < 4; nt++)
                    mma_tf32(acc[mt][nt], af[mt], bf[nt], acc[mt][nt]);
        }
        __syncthreads();
    }

    #pragma unroll
    for (int mt = 0; mt < 4; mt++) {
        int row0 = by * 128 + wm + mt * 16 + grp;
        #pragma unroll
        for (int nt = 0; nt < 4; nt++) {
            int col0 = bx * 128 + wn + nt * 8 + tig * 2;
            float b0 = bias[col0], b1 = bias[col0 + 1];
            float2 o0 = make_float2(acc[mt][nt][0] + b0, acc[mt][nt][1] + b1);
            float2 o1 = make_float2(acc[mt][nt][2] + b0, acc[mt][nt][3] + b1);
            *(float2*)(C + (size_t)row0 * Nd + col0) = o0;
            *(float2*)(C + (size_t)(row0 + 8) * Nd + col0) = o1;
        }
    }
}

// ---------------------------------------------------------------------------
// Landmarks v2: grid (BH, 8), 256 threads; one warp per landmark row.
// Coalesced 256B reads per (token, tensor) pair.
// ---------------------------------------------------------------------------
__global__ __launch_bounds__(256)
void landmarks_kernel() {
    int bh = blockIdx.x;
    int b = bh / HH, h = bh % HH;
    int w = threadIdx.x >> 5, lane = threadIdx.x & 31;
    int m = blockIdx.y * 8 + w;

    float sq0 = 0.f, sq1 = 0.f, sk0 = 0.f, sk1 = 0.f;
    size_t base = ((size_t)(b * TT + m * LL)) * (3 * EE) + h * HD;
    #pragma unroll 4
    for (int g = 0; g < LL; g++) {
        const float* row = g_qkv + base + (size_t)g * 3 * EE;
        sq0 += row[lane];
        sq1 += row[lane + 32];
        sk0 += row[EE + lane];
        sk1 += row[EE + lane + 32];
    }
    float* qo = g_qland + (bh * MM + m) * HD;
    float* ko = g_kland + (bh * MM + m) * HD;
    qo[lane]      = sq0 * (1.0f / LL) * 0.125f;
    qo[lane + 32] = sq1 * (1.0f / LL) * 0.125f;
    ko[lane]      = sk0 * (1.0f / LL);
    ko[lane + 32] = sk1 * (1.0f / LL);
}

// ---------------------------------------------------------------------------
// A = softmax(tril-mask(q_land @ k_land^T)); also per-bh max col-sum / row-sum.
// ---------------------------------------------------------------------------
__global__ void A_kernel() {
    int bh = blockIdx.x;
    __shared__ float kt[64 * 64];
    __shared__ float S[64 * 64];
    __shared__ float cbuf[64], rbuf[64];
    int tid = threadIdx.x;

    for (int idx = tid; idx < 4096; idx += 256) {
        int j = idx >> 6, d = idx & 63;
        kt[d * 64 + ((j + d) & 63)] = g_kland[bh * 4096 + j * 64 + d];
    }
    __syncthreads();

    const float* ql = g_qland + bh * 4096;
    for (int idx = tid; idx < 4096; idx += 256) {
        int i = idx >> 6, j = idx & 63;
        if (j <= i) {
            float s = 0.f;
            #pragma unroll 8
            for (int d = 0; d < 64; d++) s += ql[i * 64 + d] * kt[d * 64 + ((j + d) & 63)];
            S[idx] = s;
        } else {
            S[idx] = -INFINITY;
        }
    }
    __syncthreads();

    int w = tid / 32, lane = tid % 32;
    for (int r = 0; r < 8; r++) {
        int i = w * 8 + r;
        float v0 = S[i * 64 + lane], v1 = S[i * 64 + lane + 32];
        float mx = fmaxf(v0, v1);
        for (int o = 16; o > 0; o >>= 1) mx = fmaxf(mx, __shfl_xor_sync(0xffffffffu, mx, o));
        float e0 = expf(v0 - mx), e1 = expf(v1 - mx);
        float sm = e0 + e1;
        for (int o = 16; o > 0; o >>= 1) sm += __shfl_xor_sync(0xffffffffu, sm, o);
        float inv = 1.0f / sm;
        S[i * 64 + lane] = e0 * inv;
        S[i * 64 + lane + 32] = e1 * inv;
    }
    __syncthreads();

    for (int idx = tid; idx < 4096; idx += 256) g_A[bh * 4096 + idx] = S[idx];

    if (tid < 64) {
        float cs = 0.f, rs = 0.f;
        for (int i = 0; i < 64; i++) { cs += S[i * 64 + tid]; rs += S[tid * 64 + i]; }
        cbuf[tid] = cs; rbuf[tid] = rs;
    }
    __syncthreads();
    if (tid == 0) {
        float cm = cbuf[0], rm = rbuf[0];
        for (int i = 1; i < 64; i++) { cm = fmaxf(cm, cbuf[i]); rm = fmaxf(rm, rbuf[i]); }
        g_sums[bh * 2 + 0] = cm;
        g_sums[bh * 2 + 1] = rm;
    }
}

// ---------------------------------------------------------------------------
// Tensor-core 64x64 matmul on shared memory (256 threads = 8 warps).
// C = scale * L @ R'  where R' = (NEG ? dc*I - R : R).
// All smem values are tf32-pre-rounded -> fragment loads need no cvt.
// Stride PS=68 floats: A-frag loads conflict-free, B-frag 2-way.
// Warp w: m-band (w&3)*16, n-half (w>>2)*32 (4 n-tiles of 8).
// ---------------------------------------------------------------------------
#define PS 68

template<bool NEG>
__device__ __forceinline__ void mmtc(float* __restrict__ C,
                                     const float* __restrict__ L,
                                     const float* __restrict__ R,
                                     float dc, float scale) {
    int wid = threadIdx.x >> 5, lane = threadIdx.x & 31;
    int grp = lane >> 2, tig = lane & 3;
    int m0 = (wid & 3) * 16, n0 = (wid >> 2) * 32;

    float acc[4][4];
    #pragma unroll
    for (int nt = 0; nt < 4; nt++)
        #pragma unroll
        for (int r = 0; r < 4; r++) acc[nt][r] = 0.f;

    #pragma unroll
    for (int kk = 0; kk < 64; kk += 8) {
        uint32_t a[4];
        a[0] = __float_as_uint(L[(m0 + grp) * PS + kk + tig]);
        a[1] = __float_as_uint(L[(m0 + grp + 8) * PS + kk + tig]);
        a[2] = __float_as_uint(L[(m0 + grp) * PS + kk + tig + 4]);
        a[3] = __float_as_uint(L[(m0 + grp + 8) * PS + kk + tig + 4]);
        #pragma unroll
        for (int nt = 0; nt < 4; nt++) {
            int n = n0 + nt * 8 + grp;
            float b0v = R[(kk + tig) * PS + n];
            float b1v = R[(kk + tig + 4) * PS + n];
            uint32_t b[2];
            if (NEG) {
                b0v = ((kk + tig) == n ? dc : 0.f) - b0v;
                b1v = ((kk + tig + 4) == n ? dc : 0.f) - b1v;
                b[0] = tf32r(b0v);
                b[1] = tf32r(b1v);
            } else {
                b[0] = __float_as_uint(b0v);
                b[1] = __float_as_uint(b1v);
            }
            mma_tf32(acc[nt], a, b, acc[nt]);
        }
    }

    // C never aliases L or R in our call sequence -> write then barrier.
    #pragma unroll
    for (int nt = 0; nt < 4; nt++) {
        int c0 = n0 + nt * 8 + tig * 2;
        C[(m0 + grp) * PS + c0]         = tf32f(acc[nt][0] * scale);
        C[(m0 + grp) * PS + c0 + 1]     = tf32f(acc[nt][1] * scale);
        C[(m0 + grp + 8) * PS + c0]     = tf32f(acc[nt][2] * scale);
        C[(m0 + grp + 8) * PS + c0 + 1] = tf32f(acc[nt][3] * scale);
    }
    __syncthreads();
}

// ---------------------------------------------------------------------------
// Moore-Penrose iterative pinv, 6 iterations, per (b,h). 256 threads.
// TF32 tensor-core matmuls; all buffers tf32-rounded in smem (~87KB).
// ---------------------------------------------------------------------------
__global__ __launch_bounds__(256)
void pinv_kernel() {
    extern __shared__ float sm[];
    float* As = sm;
    float* W0 = sm + 1 * 64 * PS;
    float* W1 = sm + 2 * 64 * PS;
    float* W2 = sm + 3 * 64 * PS;
    float* W3 = sm + 4 * 64 * PS;

    int bh = blockIdx.x;
    int tid = threadIdx.x;

    float cm = 0.f, rm = 0.f;
    #pragma unroll
    for (int i = 0; i < BH; i++) {
        cm = fmaxf(cm, g_sums[2 * i + 0]);
        rm = fmaxf(rm, g_sums[2 * i + 1]);
    }
    float inv = 1.0f / (cm * rm);

    const float* Ag = g_A + bh * 4096;
    for (int idx = tid; idx < 4096; idx += 256) {
        int i = idx >> 6, j = idx & 63;
        As[i * PS + j] = tf32f(Ag[idx]);
    }
    __syncthreads();
    // z0 = A^T * inv (from the already tf32-rounded A; then re-round product)
    for (int idx = tid; idx < 4096; idx += 256) {
        int i = idx >> 6, j = idx & 63;
        W0[i * PS + j] = tf32f(As[j * PS + i] * inv);
    }
    __syncthreads();

    float* z = W0;
    float* x = W1;
    for (int it = 0; it < 6; it++) {
        mmtc<false>(x,  As, z,  0.f,  1.0f);   // xz = A @ z
        mmtc<true >(W2, x,  x,  7.f,  1.0f);   // t1 = xz @ (7I - xz)
        mmtc<true >(W3, x,  W2, 15.f, 1.0f);   // t2 = xz @ (15I - t1)
        mmtc<true >(x,  z,  W3, 13.f, 0.25f);  // z' = 0.25 z @ (13I - t2)
        float* tmp = z; z = x; x = tmp;
    }

    for (int idx = tid; idx < 4096; idx += 256) {
        int i = idx >> 6, j = idx & 63;
        g_z[bh * 4096 + idx] = z[i * PS + j];
    }
}

// ---------------------------------------------------------------------------
// Bv + zB: B_t nonzero only in first 64 columns.
// ---------------------------------------------------------------------------
__global__ void Bv_kernel() {
    int bh = blockIdx.x;
    int b = bh / HH, h = bh % HH;
    __shared__ float kt[64 * 64];
    __shared__ float S[64 * 64];
    __shared__ float B3[64 * 64];
    int tid = threadIdx.x;

    for (int idx = tid; idx < 4096; idx += 256) {
        int j = idx >> 6, d = idx & 63;
        kt[d * 64 + ((j + d) & 63)] = g_qkv[((size_t)(b * TT + j)) * 3 * EE + EE + h * HD + d];
    }
    __syncthreads();

    const float* ql = g_qland + bh * 4096;
    for (int idx = tid; idx < 4096; idx += 256) {
        int i = idx >> 6, j = idx & 63;
        if (j <= i) {
            float s = 0.f;
            #pragma unroll 8
            for (int d = 0; d < 64; d++) s += ql[i * 64 + d] * kt[d * 64 + ((j + d) & 63)];
            S[idx] = s;
        } else {
            S[idx] = -INFINITY;
        }
    }
    __syncthreads();

    int w = tid / 32, lane = tid % 32;
    for (int r = 0; r < 8; r++) {
        int i = w * 8 + r;
        float v0 = S[i * 64 + lane], v1 = S[i * 64 + lane + 32];
        float mx = fmaxf(v0, v1);
        for (int o = 16; o > 0; o >>= 1) mx = fmaxf(mx, __shfl_xor_sync(0xffffffffu, mx, o));
        float e0 = expf(v0 - mx), e1 = expf(v1 - mx);
        float sm = e0 + e1;
        for (int o = 16; o > 0; o >>= 1) sm += __shfl_xor_sync(0xffffffffu, sm, o);
        float inv = 1.0f / sm;
        S[i * 64 + lane] = e0 * inv;
        S[i * 64 + lane + 32] = e1 * inv;
    }
    __syncthreads();

    for (int idx = tid; idx < 4096; idx += 256) {
        int j = idx >> 6, d = idx & 63;
        kt[j * 64 + d] = g_qkv[((size_t)(b * TT + j)) * 3 * EE + 2 * EE + h * HD + d];
    }
    __syncthreads();

    for (int idx = tid; idx < 4096; idx += 256) {
        int i = idx >> 6, d = idx & 63;
        float s = 0.f;
        #pragma unroll 8
        for (int k = 0; k < 64; k++) s += S[i * 64 + k] * kt[k * 64 + d];
        B3[idx] = s;
    }
    __syncthreads();

    const float* z = g_z + bh * 4096;
    for (int idx = tid; idx < 4096; idx += 256) {
        int i = idx >> 6, d = idx & 63;
        float s = 0.f;
        #pragma unroll 8
        for (int k = 0; k < 64; k++) s += z[i * 64 + k] * B3[k * 64 + d];
        S[idx] = s;
    }
    __syncthreads();
    for (int idx = tid; idx < 4096; idx += 256) g_zB[bh * 4096 + idx] = S[idx];
}

// ---------------------------------------------------------------------------
// Fused F@zB: F = softmax(mask(q @ k_land^T)) computed in smem, then
// y = F @ zB written directly to [B,T,E] layout. Grid (T/64, BH), 256 thr.
// ---------------------------------------------------------------------------
__global__ void FY_kernel() {
    int tt = blockIdx.x, bh = blockIdx.y;
    int b = bh / HH, h = bh % HH;
    __shared__ float kt[64 * 64];   // swizzled k_land^T; later reused for zB
    __shared__ float qs[64 * 64];   // q tile; later reused for F probs
    int tid = threadIdx.x;

    for (int idx = tid; idx < 4096; idx += 256) {
        int j = idx >> 6, d = idx & 63;
        kt[d * 64 + ((j + d) & 63)] = g_kland[bh * 4096 + j * 64 + d];
    }
    for (int idx = tid; idx < 4096; idx += 256) {
        int r = idx >> 6, d = idx & 63;
        qs[idx] = g_qkv[((size_t)(b * TT + tt * 64 + r)) * 3 * EE + h * HD + d] * 0.125f;
    }
    __syncthreads();

    int w = tid / 32, lane = tid % 32;
    for (int r = 0; r < 8; r++) {
        int row = w * 8 + r;
        int t = tt * 64 + row;
        float a0 = 0.f, a1 = 0.f;
        #pragma unroll 8
        for (int d = 0; d < 64; d++) {
            float qv = qs[row * 64 + d];
            a0 += qv * kt[d * 64 + ((lane + d) & 63)];
            a1 += qv * kt[d * 64 + ((lane + 32 + d) & 63)];
        }
        if (lane > t) a0 = -INFINITY;
        if (lane + 32 > t) a1 = -INFINITY;
        float mx = fmaxf(a0, a1);
        for (int o = 16; o > 0; o >>= 1) mx = fmaxf(mx, __shfl_xor_sync(0xffffffffu, mx, o));
        float e0 = expf(a0 - mx), e1 = expf(a1 - mx);
        float sm = e0 + e1;
        for (int o = 16; o > 0; o >>= 1) sm += __shfl_xor_sync(0xffffffffu, sm, o);
        float inv = 1.0f / sm;
        // qs[row] fully consumed by this warp; overwrite with F probs
        qs[row * 64 + lane] = e0 * inv;
        qs[row * 64 + lane + 32] = e1 * inv;
    }
    __syncthreads();

    // load zB over kt (plain layout)
    for (int idx = tid; idx < 4096; idx += 256) kt[idx] = g_zB[bh * 4096 + idx];
    __syncthreads();

    for (int r = 0; r < 8; r++) {
        int row = w * 8 + r;
        int t = tt * 64 + row;
        float a0 = 0.f, a1 = 0.f;
        #pragma unroll 8
        for (int m = 0; m < 64; m++) {
            float fv = qs[row * 64 + m];
            a0 += fv * kt[m * 64 + lane];
            a1 += fv * kt[m * 64 + lane + 32];
        }
        g_y[((size_t)(b * TT + t)) * EE + h * 64 + lane] = a0;
        g_y[((size_t)(b * TT + t)) * EE + h * 64 + lane + 32] = a1;
    }
}

// ---------------------------------------------------------------------------
extern "C" void kernel_launch(void* const* d_in, const int* in_sizes, int n_in,
                              void* d_out, int out_size) {
    const float* x      = (const float*)d_in[0];
    const float* w_qkv  = (const float*)d_in[1];
    const float* b_qkv  = (const float*)d_in[2];
    const float* w_proj = (const float*)d_in[3];
    const float* b_proj = (const float*)d_in[4];
    float* out = (float*)d_out;

    const int PINV_SMEM = 5 * 64 * PS * sizeof(float);   // 87040 B
    cudaFuncSetAttribute(pinv_kernel,
                         cudaFuncAttributeMaxDynamicSharedMemorySize, PINV_SMEM);

    float* wqkvT;  cudaGetSymbolAddress((void**)&wqkvT,  g_wqkvT);
    float* wprojT; cudaGetSymbolAddress((void**)&wprojT, g_wprojT);

    // 0. transpose weights
    transpose_kernel<<<dim3(3 * EE / 32, EE / 32), dim3(32, 8)>>>(w_qkv, wqkvT, EE, 3 * EE);
    transpose_kernel<<<dim3(EE / 32, EE / 32), dim3(32, 8)>>>(w_proj, wprojT, EE, EE);

    // 1. qkv = x @ w_qkv + b_qkv  (tf32 mma.sync)
    mma_gemm<0><<<dim3(3 * EE / 128, BB * TT / 128), 256>>>(x, b_qkv, nullptr, 3 * EE);
    // 2. landmarks
    landmarks_kernel<<<dim3(BH, 8), 256>>>();
    // 3. A softmax + sum maxima
    A_kernel<<<BH, 256>>>();
    // 4. pinv (tf32 tensor cores)
    pinv_kernel<<<BH, 256, PINV_SMEM>>>();
    // 5. Bv / zB
    Bv_kernel<<<BH, 256>>>();
    // 6+7. y = softmax(q@kl^T) @ zB  (fused)
    FY_kernel<<<dim3(TT / 64, BH), 256>>>();
    // 8. out = y @ w_proj + b_proj  (tf32 mma.sync)
    mma_gemm<1><<<dim3(EE / 128, BB * TT / 128), 256>>>(nullptr, b_proj, out, EE);
}

// round 6
// speedup vs baseline: 2.4452x; 1.0250x over previous
#include <cuda_runtime.h>
#include <cuda_bf16.h>
#include <math.h>
#include <stdint.h>

// Problem constants
#define BB 2
#define TT 2048
#define EE 512
#define HH 8
#define HD 64
#define MM 64
#define LL 32
#define BH (BB*HH)

// Scratch (device globals; no runtime allocation)
__device__ float g_qkv[BB*TT*3*EE];      // 24 MB
__device__ float g_xr[BB*TT*EE];         // tf32-rounded x (16 MB)
__device__ float g_qland[BH*MM*HD];
__device__ float g_kland[BH*MM*HD];
__device__ float g_A[BH*MM*MM];
__device__ float g_z[BH*MM*MM];
__device__ float g_sums[BH*2];
__device__ float g_zB[BH*MM*HD];
__device__ float g_y[BB*TT*EE];          // 8 MB (tf32-rounded by FY)
__device__ float g_wqkvT[3*EE*EE];       // transposed + tf32-rounded w_qkv
__device__ float g_wprojT[EE*EE];        // transposed + tf32-rounded w_proj

__device__ __forceinline__ uint32_t tf32r(float x) {
    uint32_t r; asm("cvt.rna.tf32.f32 %0, %1;" : "=r"(r) : "f"(x)); return r;
}
__device__ __forceinline__ float tf32f(float x) {
    return __uint_as_float(tf32r(x));
}
__device__ __forceinline__ uint32_t smem_u32(const void* p) {
    uint32_t a;
    asm("{ .reg .u64 t; cvta.to.shared.u64 t, %1; cvt.u32.u64 %0, t; }" : "=r"(a) : "l"(p));
    return a;
}
__device__ __forceinline__ void cp16(uint32_t s, const void* g) {
    asm volatile("cp.async.cg.shared.global [%0], [%1], 16;" :: "r"(s), "l"(g));
}
#define CP_COMMIT() asm volatile("cp.async.commit_group;" ::: "memory")
#define CP_WAIT(n)  asm volatile("cp.async.wait_group %0;" :: "n"(n) : "memory")

__device__ __forceinline__ void mma_tf32(float* d, const uint32_t* a,
                                         const uint32_t* b, const float* c) {
    asm volatile(
        "mma.sync.aligned.m16n8k8.row.col.f32.tf32.tf32.f32 "
        "{%0,%1,%2,%3}, {%4,%5,%6,%7}, {%8,%9}, {%10,%11,%12,%13};"
        : "=f"(d[0]), "=f"(d[1]), "=f"(d[2]), "=f"(d[3])
        : "r"(a[0]), "r"(a[1]), "r"(a[2]), "r"(a[3]),
          "r"(b[0]), "r"(b[1]),
          "f"(c[0]), "f"(c[1]), "f"(c[2]), "f"(c[3]));
}

// ---------------------------------------------------------------------------
// Round x to tf32 (elementwise, float4).
// ---------------------------------------------------------------------------
__global__ void round_kernel(const float* __restrict__ src, float* __restrict__ dst) {
    int i = (blockIdx.x * 256 + threadIdx.x) * 4;
    float4 v = *(const float4*)(src + i);
    v.x = tf32f(v.x); v.y = tf32f(v.y); v.z = tf32f(v.z); v.w = tf32f(v.w);
    *(float4*)(dst + i) = v;
}

// ---------------------------------------------------------------------------
// Weight transpose + tf32 rounding: src[K,N] -> dst[N,K]
// ---------------------------------------------------------------------------
__global__ void transpose_kernel(const float* __restrict__ src, float* __restrict__ dst,
                                 int K, int N) {
    __shared__ float t[32][33];
    int bx = blockIdx.x * 32;   // N
    int by = blockIdx.y * 32;   // K
    int x = threadIdx.x;
    for (int y = threadIdx.y; y < 32; y += 8)
        t[y][x] = src[(size_t)(by + y) * N + bx + x];
    __syncthreads();
    for (int y = threadIdx.y; y < 32; y += 8)
        dst[(size_t)(bx + y) * K + by + x] = tf32f(t[x][y]);
}

// ---------------------------------------------------------------------------
// TF32 mma.sync GEMM, cp.async double-buffered:
//   C[4096, Nd] = A[4096, 512] @ BT[Nd, 512]^T + bias
// MODE 0: A = g_xr, BT = g_wqkvT, C = g_qkv
// MODE 1: A = g_y,  BT = g_wprojT, C = out (param)
// Operands are pre-rounded to tf32 in global memory -> no cvt in the loop.
// CTA 128x128, BK=32, 256 threads, warp tile 64x32. Dyn smem 72KB (2 stages).
// ---------------------------------------------------------------------------
#define GBK 32
#define GSTRIDE 36
#define STG_F (128 * GSTRIDE)            // floats per matrix per stage

template<int MODE>
__global__ __launch_bounds__(256)
void mma_gemm(const float* __restrict__ bias, float* __restrict__ Cout, int Nd) {
    extern __shared__ float sm[];
    // layout: A stage0, A stage1, B stage0, B stage1
    uint32_t sbase = smem_u32(sm);

    const float* A  = (MODE == 0) ? g_xr : g_y;
    const float* BT = (MODE == 0) ? g_wqkvT : g_wprojT;
    float* C;
    if (MODE == 0) C = g_qkv; else C = Cout;

    int tid = threadIdx.x, wid = tid >> 5, lane = tid & 31;
    int bx = blockIdx.x, by = blockIdx.y;
    int wm = (wid >> 2) * 64;
    int wn = (wid & 3) * 32;
    int grp = lane >> 2;
    int tig = lane & 3;

    const float* Abase = A  + (size_t)by * 128 * EE;
    const float* Bbase = BT + (size_t)bx * 128 * EE;

    // this thread's 4 copy slots (row, col4) for each matrix
    int cr[4], cc[4];
    #pragma unroll
    for (int i = 0; i < 4; i++) {
        int s = tid + i * 256;
        cr[i] = s >> 3;
        cc[i] = (s & 7) * 4;
    }

    float acc[4][4][4];
    #pragma unroll
    for (int mt = 0; mt < 4; mt++)
        #pragma unroll
        for (int nt = 0; nt < 4; nt++)
            #pragma unroll
            for (int r = 0; r < 4; r++) acc[mt][nt][r] = 0.f;

    // async load of chunk c into buffer buf
    auto load_chunk = [&](int c, int buf) {
        int k0 = c * GBK;
        uint32_t a_s = sbase + (uint32_t)(buf * STG_F) * 4;
        uint32_t b_s = sbase + (uint32_t)((2 + buf) * STG_F) * 4;
        #pragma unroll
        for (int i = 0; i < 4; i++) {
            uint32_t off = (uint32_t)(cr[i] * GSTRIDE + cc[i]) * 4;
            cp16(a_s + off, Abase + (size_t)cr[i] * EE + k0 + cc[i]);
            cp16(b_s + off, Bbase + (size_t)cr[i] * EE + k0 + cc[i]);
        }
    };

    load_chunk(0, 0);
    CP_COMMIT();

    const int NCH = EE / GBK;   // 16
    for (int c = 0; c < NCH; c++) {
        int buf = c & 1;
        if (c + 1 < NCH) { load_chunk(c + 1, buf ^ 1); CP_COMMIT(); CP_WAIT(1); }
        else             { CP_WAIT(0); }
        __syncthreads();

        const float* As = sm + buf * STG_F;
        const float* Bs = sm + (2 + buf) * STG_F;

        #pragma unroll
        for (int kk = 0; kk < GBK; kk += 8) {
            uint32_t af[4][4], bf[4][2];
            #pragma unroll
            for (int mt = 0; mt < 4; mt++) {
                int m = wm + mt * 16;
                af[mt][0] = __float_as_uint(As[(m + grp) * GSTRIDE + kk + tig]);
                af[mt][1] = __float_as_uint(As[(m + grp + 8) * GSTRIDE + kk + tig]);
                af[mt][2] = __float_as_uint(As[(m + grp) * GSTRIDE + kk + tig + 4]);
                af[mt][3] = __float_as_uint(As[(m + grp + 8) * GSTRIDE + kk + tig + 4]);
            }
            #pragma unroll
            for (int nt = 0; nt < 4; nt++) {
                int n = wn + nt * 8;
                bf[nt][0] = __float_as_uint(Bs[(n + grp) * GSTRIDE + kk + tig]);
                bf[nt][1] = __float_as_uint(Bs[(n + grp) * GSTRIDE + kk + tig + 4]);
            }
            #pragma unroll
            for (int mt = 0; mt < 4; mt++)
                #pragma unroll
                for (int nt = 0; nt < 4; nt++)
                    mma_tf32(acc[mt][nt], af[mt], bf[nt], acc[mt][nt]);
        }
        __syncthreads();
    }

    #pragma unroll
    for (int mt = 0; mt < 4; mt++) {
        int row0 = by * 128 + wm + mt * 16 + grp;
        #pragma unroll
        for (int nt = 0; nt < 4; nt++) {
            int col0 = bx * 128 + wn + nt * 8 + tig * 2;
            float b0 = bias[col0], b1 = bias[col0 + 1];
            float2 o0 = make_float2(acc[mt][nt][0] + b0, acc[mt][nt][1] + b1);
            float2 o1 = make_float2(acc[mt][nt][2] + b0, acc[mt][nt][3] + b1);
            *(float2*)(C + (size_t)row0 * Nd + col0) = o0;
            *(float2*)(C + (size_t)(row0 + 8) * Nd + col0) = o1;
        }
    }
}
#define GEMM_SMEM (4 * STG_F * 4)   // 73728 B

// ---------------------------------------------------------------------------
// Landmarks: grid (BH, 8), one warp per landmark row.
// ---------------------------------------------------------------------------
__global__ __launch_bounds__(256)
void landmarks_kernel() {
    int bh = blockIdx.x;
    int b = bh / HH, h = bh % HH;
    int w = threadIdx.x >> 5, lane = threadIdx.x & 31;
    int m = blockIdx.y * 8 + w;

    float sq0 = 0.f, sq1 = 0.f, sk0 = 0.f, sk1 = 0.f;
    size_t base = ((size_t)(b * TT + m * LL)) * (3 * EE) + h * HD;
    #pragma unroll 4
    for (int g = 0; g < LL; g++) {
        const float* row = g_qkv + base + (size_t)g * 3 * EE;
        sq0 += row[lane];
        sq1 += row[lane + 32];
        sk0 += row[EE + lane];
        sk1 += row[EE + lane + 32];
    }
    float* qo = g_qland + (bh * MM + m) * HD;
    float* ko = g_kland + (bh * MM + m) * HD;
    qo[lane]      = sq0 * (1.0f / LL) * 0.125f;
    qo[lane + 32] = sq1 * (1.0f / LL) * 0.125f;
    ko[lane]      = sk0 * (1.0f / LL);
    ko[lane + 32] = sk1 * (1.0f / LL);
}

// ---------------------------------------------------------------------------
// A = softmax(tril-mask(q_land @ k_land^T)); also per-bh max col-sum / row-sum.
// ---------------------------------------------------------------------------
__global__ void A_kernel() {
    int bh = blockIdx.x;
    __shared__ float kt[64 * 64];
    __shared__ float S[64 * 64];
    __shared__ float cbuf[64], rbuf[64];
    int tid = threadIdx.x;

    for (int idx = tid; idx < 4096; idx += 256) {
        int j = idx >> 6, d = idx & 63;
        kt[d * 64 + ((j + d) & 63)] = g_kland[bh * 4096 + j * 64 + d];
    }
    __syncthreads();

    const float* ql = g_qland + bh * 4096;
    for (int idx = tid; idx < 4096; idx += 256) {
        int i = idx >> 6, j = idx & 63;
        if (j <= i) {
            float s = 0.f;
            #pragma unroll 8
            for (int d = 0; d < 64; d++) s += ql[i * 64 + d] * kt[d * 64 + ((j + d) & 63)];
            S[idx] = s;
        } else {
            S[idx] = -INFINITY;
        }
    }
    __syncthreads();

    int w = tid / 32, lane = tid % 32;
    for (int r = 0; r < 8; r++) {
        int i = w * 8 + r;
        float v0 = S[i * 64 + lane], v1 = S[i * 64 + lane + 32];
        float mx = fmaxf(v0, v1);
        for (int o = 16; o > 0; o >>= 1) mx = fmaxf(mx, __shfl_xor_sync(0xffffffffu, mx, o));
        float e0 = expf(v0 - mx), e1 = expf(v1 - mx);
        float sm = e0 + e1;
        for (int o = 16; o > 0; o >>= 1) sm += __shfl_xor_sync(0xffffffffu, sm, o);
        float inv = 1.0f / sm;
        S[i * 64 + lane] = e0 * inv;
        S[i * 64 + lane + 32] = e1 * inv;
    }
    __syncthreads();

    for (int idx = tid; idx < 4096; idx += 256) g_A[bh * 4096 + idx] = S[idx];

    if (tid < 64) {
        float cs = 0.f, rs = 0.f;
        for (int i = 0; i < 64; i++) { cs += S[i * 64 + tid]; rs += S[tid * 64 + i]; }
        cbuf[tid] = cs; rbuf[tid] = rs;
    }
    __syncthreads();
    if (tid == 0) {
        float cm = cbuf[0], rm = rbuf[0];
        for (int i = 1; i < 64; i++) { cm = fmaxf(cm, cbuf[i]); rm = fmaxf(rm, rbuf[i]); }
        g_sums[bh * 2 + 0] = cm;
        g_sums[bh * 2 + 1] = rm;
    }
}

// ---------------------------------------------------------------------------
// Tensor-core 64x64 matmul on shared memory (256 threads = 8 warps).
// C = scale * L @ R'  where R' = (NEG ? dc*I - R : R). PS=68 padding.
// ---------------------------------------------------------------------------
#define PS 68

template<bool NEG>
__device__ __forceinline__ void mmtc(float* __restrict__ C,
                                     const float* __restrict__ L,
                                     const float* __restrict__ R,
                                     float dc, float scale) {
    int wid = threadIdx.x >> 5, lane = threadIdx.x & 31;
    int grp = lane >> 2, tig = lane & 3;
    int m0 = (wid & 3) * 16, n0 = (wid >> 2) * 32;

    float acc[4][4];
    #pragma unroll
    for (int nt = 0; nt < 4; nt++)
        #pragma unroll
        for (int r = 0; r < 4; r++) acc[nt][r] = 0.f;

    #pragma unroll
    for (int kk = 0; kk < 64; kk += 8) {
        uint32_t a[4];
        a[0] = __float_as_uint(L[(m0 + grp) * PS + kk + tig]);
        a[1] = __float_as_uint(L[(m0 + grp + 8) * PS + kk + tig]);
        a[2] = __float_as_uint(L[(m0 + grp) * PS + kk + tig + 4]);
        a[3] = __float_as_uint(L[(m0 + grp + 8) * PS + kk + tig + 4]);
        #pragma unroll
        for (int nt = 0; nt < 4; nt++) {
            int n = n0 + nt * 8 + grp;
            float b0v = R[(kk + tig) * PS + n];
            float b1v = R[(kk + tig + 4) * PS + n];
            uint32_t b[2];
            if (NEG) {
                b0v = ((kk + tig) == n ? dc : 0.f) - b0v;
                b1v = ((kk + tig + 4) == n ? dc : 0.f) - b1v;
                b[0] = tf32r(b0v);
                b[1] = tf32r(b1v);
            } else {
                b[0] = __float_as_uint(b0v);
                b[1] = __float_as_uint(b1v);
            }
            mma_tf32(acc[nt], a, b, acc[nt]);
        }
    }

    #pragma unroll
    for (int nt = 0; nt < 4; nt++) {
        int c0 = n0 + nt * 8 + tig * 2;
        C[(m0 + grp) * PS + c0]         = tf32f(acc[nt][0] * scale);
        C[(m0 + grp) * PS + c0 + 1]     = tf32f(acc[nt][1] * scale);
        C[(m0 + grp + 8) * PS + c0]     = tf32f(acc[nt][2] * scale);
        C[(m0 + grp + 8) * PS + c0 + 1] = tf32f(acc[nt][3] * scale);
    }
    __syncthreads();
}

// ---------------------------------------------------------------------------
// Moore-Penrose iterative pinv (tf32 tensor cores), 6 iters, per (b,h).
// ---------------------------------------------------------------------------
__global__ __launch_bounds__(256)
void pinv_kernel() {
    extern __shared__ float sm[];
    float* As = sm;
    float* W0 = sm + 1 * 64 * PS;
    float* W1 = sm + 2 * 64 * PS;
    float* W2 = sm + 3 * 64 * PS;
    float* W3 = sm + 4 * 64 * PS;

    int bh = blockIdx.x;
    int tid = threadIdx.x;

    float cm = 0.f, rm = 0.f;
    #pragma unroll
    for (int i = 0; i < BH; i++) {
        cm = fmaxf(cm, g_sums[2 * i + 0]);
        rm = fmaxf(rm, g_sums[2 * i + 1]);
    }
    float inv = 1.0f / (cm * rm);

    const float* Ag = g_A + bh * 4096;
    for (int idx = tid; idx < 4096; idx += 256) {
        int i = idx >> 6, j = idx & 63;
        As[i * PS + j] = tf32f(Ag[idx]);
    }
    __syncthreads();
    for (int idx = tid; idx < 4096; idx += 256) {
        int i = idx >> 6, j = idx & 63;
        W0[i * PS + j] = tf32f(As[j * PS + i] * inv);
    }
    __syncthreads();

    float* z = W0;
    float* x = W1;
    for (int it = 0; it < 6; it++) {
        mmtc<false>(x,  As, z,  0.f,  1.0f);
        mmtc<true >(W2, x,  x,  7.f,  1.0f);
        mmtc<true >(W3, x,  W2, 15.f, 1.0f);
        mmtc<true >(x,  z,  W3, 13.f, 0.25f);
        float* tmp = z; z = x; x = tmp;
    }

    for (int idx = tid; idx < 4096; idx += 256) {
        int i = idx >> 6, j = idx & 63;
        g_z[bh * 4096 + idx] = z[i * PS + j];
    }
}

// ---------------------------------------------------------------------------
// Bv + zB: B_t nonzero only in first 64 columns.
// ---------------------------------------------------------------------------
__global__ void Bv_kernel() {
    int bh = blockIdx.x;
    int b = bh / HH, h = bh % HH;
    __shared__ float kt[64 * 64];
    __shared__ float S[64 * 64];
    __shared__ float B3[64 * 64];
    int tid = threadIdx.x;

    for (int idx = tid; idx < 4096; idx += 256) {
        int j = idx >> 6, d = idx & 63;
        kt[d * 64 + ((j + d) & 63)] = g_qkv[((size_t)(b * TT + j)) * 3 * EE + EE + h * HD + d];
    }
    __syncthreads();

    const float* ql = g_qland + bh * 4096;
    for (int idx = tid; idx < 4096; idx += 256) {
        int i = idx >> 6, j = idx & 63;
        if (j <= i) {
            float s = 0.f;
            #pragma unroll 8
            for (int d = 0; d < 64; d++) s += ql[i * 64 + d] * kt[d * 64 + ((j + d) & 63)];
            S[idx] = s;
        } else {
            S[idx] = -INFINITY;
        }
    }
    __syncthreads();

    int w = tid / 32, lane = tid % 32;
    for (int r = 0; r < 8; r++) {
        int i = w * 8 + r;
        float v0 = S[i * 64 + lane], v1 = S[i * 64 + lane + 32];
        float mx = fmaxf(v0, v1);
        for (int o = 16; o > 0; o >>= 1) mx = fmaxf(mx, __shfl_xor_sync(0xffffffffu, mx, o));
        float e0 = expf(v0 - mx), e1 = expf(v1 - mx);
        float sm = e0 + e1;
        for (int o = 16; o > 0; o >>= 1) sm += __shfl_xor_sync(0xffffffffu, sm, o);
        float inv = 1.0f / sm;
        S[i * 64 + lane] = e0 * inv;
        S[i * 64 + lane + 32] = e1 * inv;
    }
    __syncthreads();

    for (int idx = tid; idx < 4096; idx += 256) {
        int j = idx >> 6, d = idx & 63;
        kt[j * 64 + d] = g_qkv[((size_t)(b * TT + j)) * 3 * EE + 2 * EE + h * HD + d];
    }
    __syncthreads();

    for (int idx = tid; idx < 4096; idx += 256) {
        int i = idx >> 6, d = idx & 63;
        float s = 0.f;
        #pragma unroll 8
        for (int k = 0; k < 64; k++) s += S[i * 64 + k] * kt[k * 64 + d];
        B3[idx] = s;
    }
    __syncthreads();

    const float* z = g_z + bh * 4096;
    for (int idx = tid; idx < 4096; idx += 256) {
        int i = idx >> 6, d = idx & 63;
        float s = 0.f;
        #pragma unroll 8
        for (int k = 0; k < 64; k++) s += z[i * 64 + k] * B3[k * 64 + d];
        S[idx] = s;
    }
    __syncthreads();
    for (int idx = tid; idx < 4096; idx += 256) g_zB[bh * 4096 + idx] = S[idx];
}

// ---------------------------------------------------------------------------
// Fused F@zB; writes y tf32-rounded (proj GEMM reads it raw).
// ---------------------------------------------------------------------------
__global__ void FY_kernel() {
    int tt = blockIdx.x, bh = blockIdx.y;
    int b = bh / HH, h = bh % HH;
    __shared__ float kt[64 * 64];
    __shared__ float qs[64 * 64];
    int tid = threadIdx.x;

    for (int idx = tid; idx < 4096; idx += 256) {
        int j = idx >> 6, d = idx & 63;
        kt[d * 64 + ((j + d) & 63)] = g_kland[bh * 4096 + j * 64 + d];
    }
    for (int idx = tid; idx < 4096; idx += 256) {
        int r = idx >> 6, d = idx & 63;
        qs[idx] = g_qkv[((size_t)(b * TT + tt * 64 + r)) * 3 * EE + h * HD + d] * 0.125f;
    }
    __syncthreads();

    int w = tid / 32, lane = tid % 32;
    for (int r = 0; r < 8; r++) {
        int row = w * 8 + r;
        int t = tt * 64 + row;
        float a0 = 0.f, a1 = 0.f;
        #pragma unroll 8
        for (int d = 0; d < 64; d++) {
            float qv = qs[row * 64 + d];
            a0 += qv * kt[d * 64 + ((lane + d) & 63)];
            a1 += qv * kt[d * 64 + ((lane + 32 + d) & 63)];
        }
        if (lane > t) a0 = -INFINITY;
        if (lane + 32 > t) a1 = -INFINITY;
        float mx = fmaxf(a0, a1);
        for (int o = 16; o > 0; o >>= 1) mx = fmaxf(mx, __shfl_xor_sync(0xffffffffu, mx, o));
        float e0 = expf(a0 - mx), e1 = expf(a1 - mx);
        float sm = e0 + e1;
        for (int o = 16; o > 0; o >>= 1) sm += __shfl_xor_sync(0xffffffffu, sm, o);
        float inv = 1.0f / sm;
        qs[row * 64 + lane] = e0 * inv;
        qs[row * 64 + lane + 32] = e1 * inv;
    }
    __syncthreads();

    for (int idx = tid; idx < 4096; idx += 256) kt[idx] = g_zB[bh * 4096 + idx];
    __syncthreads();

    for (int r = 0; r < 8; r++) {
        int row = w * 8 + r;
        int t = tt * 64 + row;
        float a0 = 0.f, a1 = 0.f;
        #pragma unroll 8
        for (int m = 0; m < 64; m++) {
            float fv = qs[row * 64 + m];
            a0 += fv * kt[m * 64 + lane];
            a1 += fv * kt[m * 64 + lane + 32];
        }
        g_y[((size_t)(b * TT + t)) * EE + h * 64 + lane] = tf32f(a0);
        g_y[((size_t)(b * TT + t)) * EE + h * 64 + lane + 32] = tf32f(a1);
    }
}

// ---------------------------------------------------------------------------
extern "C" void kernel_launch(void* const* d_in, const int* in_sizes, int n_in,
                              void* d_out, int out_size) {
    const float* x      = (const float*)d_in[0];
    const float* w_qkv  = (const float*)d_in[1];
    const float* b_qkv  = (const float*)d_in[2];
    const float* w_proj = (const float*)d_in[3];
    const float* b_proj = (const float*)d_in[4];
    float* out = (float*)d_out;

    const int PINV_SMEM = 5 * 64 * PS * sizeof(float);   // 87040 B
    cudaFuncSetAttribute(pinv_kernel,
                         cudaFuncAttributeMaxDynamicSharedMemorySize, PINV_SMEM);
    cudaFuncSetAttribute(mma_gemm<0>,
                         cudaFuncAttributeMaxDynamicSharedMemorySize, GEMM_SMEM);
    cudaFuncSetAttribute(mma_gemm<1>,
                         cudaFuncAttributeMaxDynamicSharedMemorySize, GEMM_SMEM);

    float* wqkvT;  cudaGetSymbolAddress((void**)&wqkvT,  g_wqkvT);
    float* wprojT; cudaGetSymbolAddress((void**)&wprojT, g_wprojT);
    float* xr;     cudaGetSymbolAddress((void**)&xr,     g_xr);

    // 0. pre-round x; transpose+round weights
    round_kernel<<<BB * TT * EE / 1024, 256>>>(x, xr);
    transpose_kernel<<<dim3(3 * EE / 32, EE / 32), dim3(32, 8)>>>(w_qkv, wqkvT, EE, 3 * EE);
    transpose_kernel<<<dim3(EE / 32, EE / 32), dim3(32, 8)>>>(w_proj, wprojT, EE, EE);

    // 1. qkv = x @ w_qkv + b_qkv
    mma_gemm<0><<<dim3(3 * EE / 128, BB * TT / 128), 256, GEMM_SMEM>>>(b_qkv, nullptr, 3 * EE);
    // 2. landmarks
    landmarks_kernel<<<dim3(BH, 8), 256>>>();
    // 3. A softmax + sum maxima
    A_kernel<<<BH, 256>>>();
    // 4. pinv
    pinv_kernel<<<BH, 256, PINV_SMEM>>>();
    // 5. Bv / zB
    Bv_kernel<<<BH, 256>>>();
    // 6+7. y = softmax(q@kl^T) @ zB
    FY_kernel<<<dim3(TT / 64, BH), 256>>>();
    // 8. out = y @ w_proj + b_proj
    mma_gemm<1><<<dim3(EE / 128, BB * TT / 128), 256, GEMM_SMEM>>>(b_proj, out, EE);
}

// round 7
// speedup vs baseline: 3.4894x; 1.4270x over previous
#include <cuda_runtime.h>
#include <cuda_bf16.h>
#include <math.h>
#include <stdint.h>

// Problem constants
#define BB 2
#define TT 2048
#define EE 512
#define HH 8
#define HD 64
#define MM 64
#define LL 32
#define BH (BB*HH)

// Scratch (device globals; no runtime allocation)
__device__ float g_qkv[BB*TT*3*EE];      // 24 MB
__device__ float g_xr[BB*TT*EE];         // tf32-rounded x (16 MB)
__device__ float g_qland[BH*MM*HD];
__device__ float g_kland[BH*MM*HD];
__device__ float g_A[BH*MM*MM];
__device__ float g_Bv[BH*MM*HD];         // P @ v[:64]  (fp32)
__device__ float g_sums[BH*2];
__device__ float g_zB[BH*MM*HD];
__device__ float g_y[BB*TT*EE];          // 8 MB (tf32-rounded by FY)
__device__ float g_wqkvT[3*EE*EE];       // transposed + tf32-rounded w_qkv
__device__ float g_wprojT[EE*EE];        // transposed + tf32-rounded w_proj

__device__ __forceinline__ uint32_t tf32r(float x) {
    uint32_t r; asm("cvt.rna.tf32.f32 %0, %1;" : "=r"(r) : "f"(x)); return r;
}
__device__ __forceinline__ float tf32f(float x) {
    return __uint_as_float(tf32r(x));
}
__device__ __forceinline__ uint32_t smem_u32(const void* p) {
    uint32_t a;
    asm("{ .reg .u64 t; cvta.to.shared.u64 t, %1; cvt.u32.u64 %0, t; }" : "=r"(a) : "l"(p));
    return a;
}
__device__ __forceinline__ void cp16(uint32_t s, const void* g) {
    asm volatile("cp.async.cg.shared.global [%0], [%1], 16;" :: "r"(s), "l"(g));
}
#define CP_COMMIT() asm volatile("cp.async.commit_group;" ::: "memory")
#define CP_WAIT(n)  asm volatile("cp.async.wait_group %0;" :: "n"(n) : "memory")

__device__ __forceinline__ void mma_tf32(float* d, const uint32_t* a,
                                         const uint32_t* b, const float* c) {
    asm volatile(
        "mma.sync.aligned.m16n8k8.row.col.f32.tf32.tf32.f32 "
        "{%0,%1,%2,%3}, {%4,%5,%6,%7}, {%8,%9}, {%10,%11,%12,%13};"
        : "=f"(d[0]), "=f"(d[1]), "=f"(d[2]), "=f"(d[3])
        : "r"(a[0]), "r"(a[1]), "r"(a[2]), "r"(a[3]),
          "r"(b[0]), "r"(b[1]),
          "f"(c[0]), "f"(c[1]), "f"(c[2]), "f"(c[3]));
}

// ---------------------------------------------------------------------------
// Round x to tf32 (elementwise, float4).
// ---------------------------------------------------------------------------
__global__ void round_kernel(const float* __restrict__ src, float* __restrict__ dst) {
    int i = (blockIdx.x * 256 + threadIdx.x) * 4;
    float4 v = *(const float4*)(src + i);
    v.x = tf32f(v.x); v.y = tf32f(v.y); v.z = tf32f(v.z); v.w = tf32f(v.w);
    *(float4*)(dst + i) = v;
}

// ---------------------------------------------------------------------------
// Weight transpose + tf32 rounding: src[K,N] -> dst[N,K]
// ---------------------------------------------------------------------------
__global__ void transpose_kernel(const float* __restrict__ src, float* __restrict__ dst,
                                 int K, int N) {
    __shared__ float t[32][33];
    int bx = blockIdx.x * 32;   // N
    int by = blockIdx.y * 32;   // K
    int x = threadIdx.x;
    for (int y = threadIdx.y; y < 32; y += 8)
        t[y][x] = src[(size_t)(by + y) * N + bx + x];
    __syncthreads();
    for (int y = threadIdx.y; y < 32; y += 8)
        dst[(size_t)(bx + y) * K + by + x] = tf32f(t[x][y]);
}

// ---------------------------------------------------------------------------
// TF32 mma.sync GEMM, cp.async double-buffered:
//   C[4096, Nd] = A[4096, 512] @ BT[Nd, 512]^T + bias
// ---------------------------------------------------------------------------
#define GBK 32
#define GSTRIDE 36
#define STG_F (128 * GSTRIDE)

template<int MODE>
__global__ __launch_bounds__(256)
void mma_gemm(const float* __restrict__ bias, float* __restrict__ Cout, int Nd) {
    extern __shared__ float sm[];
    uint32_t sbase = smem_u32(sm);

    const float* A  = (MODE == 0) ? g_xr : g_y;
    const float* BT = (MODE == 0) ? g_wqkvT : g_wprojT;
    float* C;
    if (MODE == 0) C = g_qkv; else C = Cout;

    int tid = threadIdx.x, wid = tid >> 5, lane = tid & 31;
    int bx = blockIdx.x, by = blockIdx.y;
    int wm = (wid >> 2) * 64;
    int wn = (wid & 3) * 32;
    int grp = lane >> 2;
    int tig = lane & 3;

    const float* Abase = A  + (size_t)by * 128 * EE;
    const float* Bbase = BT + (size_t)bx * 128 * EE;

    int cr[4], cc[4];
    #pragma unroll
    for (int i = 0; i < 4; i++) {
        int s = tid + i * 256;
        cr[i] = s >> 3;
        cc[i] = (s & 7) * 4;
    }

    float acc[4][4][4];
    #pragma unroll
    for (int mt = 0; mt < 4; mt++)
        #pragma unroll
        for (int nt = 0; nt < 4; nt++)
            #pragma unroll
            for (int r = 0; r < 4; r++) acc[mt][nt][r] = 0.f;

    auto load_chunk = [&](int c, int buf) {
        int k0 = c * GBK;
        uint32_t a_s = sbase + (uint32_t)(buf * STG_F) * 4;
        uint32_t b_s = sbase + (uint32_t)((2 + buf) * STG_F) * 4;
        #pragma unroll
        for (int i = 0; i < 4; i++) {
            uint32_t off = (uint32_t)(cr[i] * GSTRIDE + cc[i]) * 4;
            cp16(a_s + off, Abase + (size_t)cr[i] * EE + k0 + cc[i]);
            cp16(b_s + off, Bbase + (size_t)cr[i] * EE + k0 + cc[i]);
        }
    };

    load_chunk(0, 0);
    CP_COMMIT();

    const int NCH = EE / GBK;
    for (int c = 0; c < NCH; c++) {
        int buf = c & 1;
        if (c + 1 < NCH) { load_chunk(c + 1, buf ^ 1); CP_COMMIT(); CP_WAIT(1); }
        else             { CP_WAIT(0); }
        __syncthreads();

        const float* As = sm + buf * STG_F;
        const float* Bs = sm + (2 + buf) * STG_F;

        #pragma unroll
        for (int kk = 0; kk < GBK; kk += 8) {
            uint32_t af[4][4], bf[4][2];
            #pragma unroll
            for (int mt = 0; mt < 4; mt++) {
                int m = wm + mt * 16;
                af[mt][0] = __float_as_uint(As[(m + grp) * GSTRIDE + kk + tig]);
                af[mt][1] = __float_as_uint(As[(m + grp + 8) * GSTRIDE + kk + tig]);
                af[mt][2] = __float_as_uint(As[(m + grp) * GSTRIDE + kk + tig + 4]);
                af[mt][3] = __float_as_uint(As[(m + grp + 8) * GSTRIDE + kk + tig + 4]);
            }
            #pragma unroll
            for (int nt = 0; nt < 4; nt++) {
                int n = wn + nt * 8;
                bf[nt][0] = __float_as_uint(Bs[(n + grp) * GSTRIDE + kk + tig]);
                bf[nt][1] = __float_as_uint(Bs[(n + grp) * GSTRIDE + kk + tig + 4]);
            }
            #pragma unroll
            for (int mt = 0; mt < 4; mt++)
                #pragma unroll
                for (int nt = 0; nt < 4; nt++)
                    mma_tf32(acc[mt][nt], af[mt], bf[nt], acc[mt][nt]);
        }
        __syncthreads();
    }

    #pragma unroll
    for (int mt = 0; mt < 4; mt++) {
        int row0 = by * 128 + wm + mt * 16 + grp;
        #pragma unroll
        for (int nt = 0; nt < 4; nt++) {
            int col0 = bx * 128 + wn + nt * 8 + tig * 2;
            float b0 = bias[col0], b1 = bias[col0 + 1];
            float2 o0 = make_float2(acc[mt][nt][0] + b0, acc[mt][nt][1] + b1);
            float2 o1 = make_float2(acc[mt][nt][2] + b0, acc[mt][nt][3] + b1);
            *(float2*)(C + (size_t)row0 * Nd + col0) = o0;
            *(float2*)(C + (size_t)(row0 + 8) * Nd + col0) = o1;
        }
    }
}
#define GEMM_SMEM (4 * STG_F * 4)   // 73728 B

// ---------------------------------------------------------------------------
// Landmarks: grid (BH, 8), one warp per landmark row.
// ---------------------------------------------------------------------------
__global__ __launch_bounds__(256)
void landmarks_kernel() {
    int bh = blockIdx.x;
    int b = bh / HH, h = bh % HH;
    int w = threadIdx.x >> 5, lane = threadIdx.x & 31;
    int m = blockIdx.y * 8 + w;

    float sq0 = 0.f, sq1 = 0.f, sk0 = 0.f, sk1 = 0.f;
    size_t base = ((size_t)(b * TT + m * LL)) * (3 * EE) + h * HD;
    #pragma unroll 4
    for (int g = 0; g < LL; g++) {
        const float* row = g_qkv + base + (size_t)g * 3 * EE;
        sq0 += row[lane];
        sq1 += row[lane + 32];
        sk0 += row[EE + lane];
        sk1 += row[EE + lane + 32];
    }
    float* qo = g_qland + (bh * MM + m) * HD;
    float* ko = g_kland + (bh * MM + m) * HD;
    qo[lane]      = sq0 * (1.0f / LL) * 0.125f;
    qo[lane + 32] = sq1 * (1.0f / LL) * 0.125f;
    ko[lane]      = sk0 * (1.0f / LL);
    ko[lane + 32] = sk1 * (1.0f / LL);
}

// ---------------------------------------------------------------------------
// AB_kernel, grid 32, dyn smem ~50KB:
//   blocks 0..15  : A = softmax(mask(ql @ kl^T)) + per-bh sum maxima
//   blocks 16..31 : Bv = softmax(mask(ql @ k[:64]^T)) @ v[:64]   (independent of z)
// ---------------------------------------------------------------------------
__global__ __launch_bounds__(256)
void AB_kernel() {
    extern __shared__ float sb[];
    float* kt = sb;            // 4096
    float* S  = sb + 4096;     // 4096
    float* B3 = sb + 8192;     // 4096 (Bv part only)
    float* cbuf = sb + 12288;  // 64
    float* rbuf = sb + 12352;  // 64

    int part = blockIdx.x >> 4;          // 0 = A, 1 = Bv
    int bh = blockIdx.x & 15;
    int b = bh / HH, h = bh % HH;
    int tid = threadIdx.x;

    // load K-side operand transposed+swizzled: kl (part 0) or k[:64] (part 1)
    for (int idx = tid; idx < 4096; idx += 256) {
        int j = idx >> 6, d = idx & 63;
        float v = (part == 0)
            ? g_kland[bh * 4096 + j * 64 + d]
            : g_qkv[((size_t)(b * TT + j)) * 3 * EE + EE + h * HD + d];
        kt[d * 64 + ((j + d) & 63)] = v;
    }
    __syncthreads();

    const float* ql = g_qland + bh * 4096;
    for (int idx = tid; idx < 4096; idx += 256) {
        int i = idx >> 6, j = idx & 63;
        if (j <= i) {
            float s = 0.f;
            #pragma unroll 8
            for (int d = 0; d < 64; d++) s += ql[i * 64 + d] * kt[d * 64 + ((j + d) & 63)];
            S[idx] = s;
        } else {
            S[idx] = -INFINITY;
        }
    }
    __syncthreads();

    int w = tid / 32, lane = tid % 32;
    for (int r = 0; r < 8; r++) {
        int i = w * 8 + r;
        float v0 = S[i * 64 + lane], v1 = S[i * 64 + lane + 32];
        float mx = fmaxf(v0, v1);
        for (int o = 16; o > 0; o >>= 1) mx = fmaxf(mx, __shfl_xor_sync(0xffffffffu, mx, o));
        float e0 = expf(v0 - mx), e1 = expf(v1 - mx);
        float sm = e0 + e1;
        for (int o = 16; o > 0; o >>= 1) sm += __shfl_xor_sync(0xffffffffu, sm, o);
        float inv = 1.0f / sm;
        S[i * 64 + lane] = e0 * inv;
        S[i * 64 + lane + 32] = e1 * inv;
    }
    __syncthreads();

    if (part == 0) {
        for (int idx = tid; idx < 4096; idx += 256) g_A[bh * 4096 + idx] = S[idx];
        if (tid < 64) {
            float cs = 0.f, rs = 0.f;
            for (int i = 0; i < 64; i++) { cs += S[i * 64 + tid]; rs += S[tid * 64 + i]; }
            cbuf[tid] = cs; rbuf[tid] = rs;
        }
        __syncthreads();
        if (tid == 0) {
            float cm = cbuf[0], rm = rbuf[0];
            for (int i = 1; i < 64; i++) { cm = fmaxf(cm, cbuf[i]); rm = fmaxf(rm, rbuf[i]); }
            g_sums[bh * 2 + 0] = cm;
            g_sums[bh * 2 + 1] = rm;
        }
    } else {
        // load v[:64] plain over kt
        for (int idx = tid; idx < 4096; idx += 256) {
            int j = idx >> 6, d = idx & 63;
            kt[j * 64 + d] = g_qkv[((size_t)(b * TT + j)) * 3 * EE + 2 * EE + h * HD + d];
        }
        __syncthreads();
        for (int idx = tid; idx < 4096; idx += 256) {
            int i = idx >> 6, d = idx & 63;
            float s = 0.f;
            #pragma unroll 8
            for (int k = 0; k < 64; k++) s += S[i * 64 + k] * kt[k * 64 + d];
            B3[idx] = s;
        }
        __syncthreads();
        for (int idx = tid; idx < 4096; idx += 256) g_Bv[bh * 4096 + idx] = B3[idx];
    }
}
#define AB_SMEM ((3 * 4096 + 128) * 4)

// ---------------------------------------------------------------------------
// Tensor-core 64x64 matmul on PS-padded smem (256 threads = 8 warps).
// C = scale * L @ R'  where R' = (NEG ? dc*I - R : R); R stored [k][n].
// RNDOUT: round C to tf32 on writeback (needed when C feeds another mma as-is).
// ---------------------------------------------------------------------------
#define PS 68

template<bool NEG, bool RNDOUT>
__device__ __forceinline__ void mmtc(float* __restrict__ C,
                                     const float* __restrict__ L,
                                     const float* __restrict__ R,
                                     float dc, float scale) {
    int wid = threadIdx.x >> 5, lane = threadIdx.x & 31;
    int grp = lane >> 2, tig = lane & 3;
    int m0 = (wid & 3) * 16, n0 = (wid >> 2) * 32;

    float acc[4][4];
    #pragma unroll
    for (int nt = 0; nt < 4; nt++)
        #pragma unroll
        for (int r = 0; r < 4; r++) acc[nt][r] = 0.f;

    #pragma unroll
    for (int kk = 0; kk < 64; kk += 8) {
        uint32_t a[4];
        a[0] = __float_as_uint(L[(m0 + grp) * PS + kk + tig]);
        a[1] = __float_as_uint(L[(m0 + grp + 8) * PS + kk + tig]);
        a[2] = __float_as_uint(L[(m0 + grp) * PS + kk + tig + 4]);
        a[3] = __float_as_uint(L[(m0 + grp + 8) * PS + kk + tig + 4]);
        #pragma unroll
        for (int nt = 0; nt < 4; nt++) {
            int n = n0 + nt * 8 + grp;
            float b0v = R[(kk + tig) * PS + n];
            float b1v = R[(kk + tig + 4) * PS + n];
            uint32_t b[2];
            if (NEG) {
                b0v = ((kk + tig) == n ? dc : 0.f) - b0v;
                b1v = ((kk + tig + 4) == n ? dc : 0.f) - b1v;
                b[0] = tf32r(b0v);
                b[1] = tf32r(b1v);
            } else {
                b[0] = __float_as_uint(b0v);
                b[1] = __float_as_uint(b1v);
            }
            mma_tf32(acc[nt], a, b, acc[nt]);
        }
    }

    #pragma unroll
    for (int nt = 0; nt < 4; nt++) {
        int c0 = n0 + nt * 8 + tig * 2;
        float o0 = acc[nt][0] * scale, o1 = acc[nt][1] * scale;
        float o2 = acc[nt][2] * scale, o3 = acc[nt][3] * scale;
        if (RNDOUT) { o0 = tf32f(o0); o1 = tf32f(o1); o2 = tf32f(o2); o3 = tf32f(o3); }
        C[(m0 + grp) * PS + c0]         = o0;
        C[(m0 + grp) * PS + c0 + 1]     = o1;
        C[(m0 + grp + 8) * PS + c0]     = o2;
        C[(m0 + grp + 8) * PS + c0 + 1] = o3;
    }
    __syncthreads();
}

// ---------------------------------------------------------------------------
// pinv + zB fused: 6 Newton-Schulz iterations, then zB = z @ Bv, per (b,h).
// ---------------------------------------------------------------------------
__global__ __launch_bounds__(256)
void pinv_kernel() {
    extern __shared__ float sm[];
    float* As = sm;
    float* W0 = sm + 1 * 64 * PS;
    float* W1 = sm + 2 * 64 * PS;
    float* W2 = sm + 3 * 64 * PS;
    float* W3 = sm + 4 * 64 * PS;

    int bh = blockIdx.x;
    int tid = threadIdx.x;

    float cm = 0.f, rm = 0.f;
    #pragma unroll
    for (int i = 0; i < BH; i++) {
        cm = fmaxf(cm, g_sums[2 * i + 0]);
        rm = fmaxf(rm, g_sums[2 * i + 1]);
    }
    float inv = 1.0f / (cm * rm);

    const float* Ag = g_A + bh * 4096;
    for (int idx = tid; idx < 4096; idx += 256) {
        int i = idx >> 6, j = idx & 63;
        As[i * PS + j] = tf32f(Ag[idx]);
    }
    __syncthreads();
    for (int idx = tid; idx < 4096; idx += 256) {
        int i = idx >> 6, j = idx & 63;
        W0[i * PS + j] = tf32f(As[j * PS + i] * inv);
    }
    __syncthreads();

    float* z = W0;
    float* x = W1;
    for (int it = 0; it < 6; it++) {
        mmtc<false, true>(x,  As, z,  0.f,  1.0f);
        mmtc<true,  true>(W2, x,  x,  7.f,  1.0f);
        mmtc<true,  true>(W3, x,  W2, 15.f, 1.0f);
        mmtc<true,  true>(x,  z,  W3, 13.f, 0.25f);
        float* tmp = z; z = x; x = tmp;
    }

    // zB = z @ Bv  (Bv raw fp32 -> round; result raw fp32)
    float* Bvs = (z == W0) ? W1 : W0;   // any free buffer != z
    for (int idx = tid; idx < 4096; idx += 256) {
        int i = idx >> 6, j = idx & 63;
        Bvs[i * PS + j] = tf32f(g_Bv[bh * 4096 + idx]);
    }
    __syncthreads();
    mmtc<false, false>(W3, z, Bvs, 0.f, 1.0f);

    for (int idx = tid; idx < 4096; idx += 256) {
        int i = idx >> 6, j = idx & 63;
        g_zB[bh * 4096 + idx] = W3[i * PS + j];
    }
}
#define PINV_SMEM (5 * 64 * PS * 4)

// ---------------------------------------------------------------------------
// Fused F@zB with tensor cores. Grid (T/64, BH), 256 threads, dyn smem 52KB.
//   S = q @ kl^T (mma) -> mask+softmax (scalar, probs rounded) -> Y = F @ zB (mma)
// ---------------------------------------------------------------------------
__global__ __launch_bounds__(256)
void FY_kernel() {
    extern __shared__ float sb[];
    float* ks = sb;              // kl^T [d][j], later zB [m][d]
    float* qs = sb + 64 * PS;    // q [row][d], later Y
    float* Ss = sb + 2 * 64 * PS; // S / F
    int tt = blockIdx.x, bh = blockIdx.y;
    int b = bh / HH, h = bh % HH;
    int tid = threadIdx.x;

    // kl^T: ks[d][j] = kl[j][d], rounded
    for (int idx = tid; idx < 4096; idx += 256) {
        int j = idx >> 6, d = idx & 63;
        ks[d * PS + j] = tf32f(g_kland[bh * 4096 + j * 64 + d]);
    }
    // q rows (pre-scaled, rounded)
    for (int idx = tid; idx < 4096; idx += 256) {
        int r = idx >> 6, d = idx & 63;
        qs[r * PS + d] = tf32f(g_qkv[((size_t)(b * TT + tt * 64 + r)) * 3 * EE + h * HD + d] * 0.125f);
    }
    __syncthreads();

    // S = q @ kl^T   (R = ks stored [k=d][n=j])
    mmtc<false, false>(Ss, qs, ks, 0.f, 1.0f);

    // mask + softmax on Ss rows; write probs tf32-rounded
    int w = tid / 32, lane = tid % 32;
    for (int r = 0; r < 8; r++) {
        int row = w * 8 + r;
        int t = tt * 64 + row;
        float a0 = Ss[row * PS + lane];
        float a1 = Ss[row * PS + lane + 32];
        if (lane > t) a0 = -INFINITY;
        if (lane + 32 > t) a1 = -INFINITY;
        float mx = fmaxf(a0, a1);
        for (int o = 16; o > 0; o >>= 1) mx = fmaxf(mx, __shfl_xor_sync(0xffffffffu, mx, o));
        float e0 = expf(a0 - mx), e1 = expf(a1 - mx);
        float sm = e0 + e1;
        for (int o = 16; o > 0; o >>= 1) sm += __shfl_xor_sync(0xffffffffu, sm, o);
        float inv = 1.0f / sm;
        Ss[row * PS + lane] = tf32f(e0 * inv);
        Ss[row * PS + lane + 32] = tf32f(e1 * inv);
    }
    __syncthreads();

    // zB into ks [k=m][n=d], rounded
    for (int idx = tid; idx < 4096; idx += 256) {
        int m = idx >> 6, d = idx & 63;
        ks[m * PS + d] = tf32f(g_zB[bh * 4096 + idx]);
    }
    __syncthreads();

    // Y = F @ zB -> qs (raw fp32)
    mmtc<false, false>(qs, Ss, ks, 0.f, 1.0f);

    // write to g_y (tf32-rounded for proj GEMM)
    for (int idx = tid; idx < 4096; idx += 256) {
        int r = idx >> 6, d = idx & 63;
        int t = tt * 64 + r;
        g_y[((size_t)(b * TT + t)) * EE + h * 64 + d] = tf32f(qs[r * PS + d]);
    }
}
#define FY_SMEM (3 * 64 * PS * 4)

// ---------------------------------------------------------------------------
extern "C" void kernel_launch(void* const* d_in, const int* in_sizes, int n_in,
                              void* d_out, int out_size) {
    const float* x      = (const float*)d_in[0];
    const float* w_qkv  = (const float*)d_in[1];
    const float* b_qkv  = (const float*)d_in[2];
    const float* w_proj = (const float*)d_in[3];
    const float* b_proj = (const float*)d_in[4];
    float* out = (float*)d_out;

    cudaFuncSetAttribute(pinv_kernel,
                         cudaFuncAttributeMaxDynamicSharedMemorySize, PINV_SMEM);
    cudaFuncSetAttribute(mma_gemm<0>,
                         cudaFuncAttributeMaxDynamicSharedMemorySize, GEMM_SMEM);
    cudaFuncSetAttribute(mma_gemm<1>,
                         cudaFuncAttributeMaxDynamicSharedMemorySize, GEMM_SMEM);
    cudaFuncSetAttribute(AB_kernel,
                         cudaFuncAttributeMaxDynamicSharedMemorySize, AB_SMEM);
    cudaFuncSetAttribute(FY_kernel,
                         cudaFuncAttributeMaxDynamicSharedMemorySize, FY_SMEM);

    float* wqkvT;  cudaGetSymbolAddress((void**)&wqkvT,  g_wqkvT);
    float* wprojT; cudaGetSymbolAddress((void**)&wprojT, g_wprojT);
    float* xr;     cudaGetSymbolAddress((void**)&xr,     g_xr);

    // 0. pre-round x; transpose+round weights
    round_kernel<<<BB * TT * EE / 1024, 256>>>(x, xr);
    transpose_kernel<<<dim3(3 * EE / 32, EE / 32), dim3(32, 8)>>>(w_qkv, wqkvT, EE, 3 * EE);
    transpose_kernel<<<dim3(EE / 32, EE / 32), dim3(32, 8)>>>(w_proj, wprojT, EE, EE);

    // 1. qkv = x @ w_qkv + b_qkv
    mma_gemm<0><<<dim3(3 * EE / 128, BB * TT / 128), 256, GEMM_SMEM>>>(b_qkv, nullptr, 3 * EE);
    // 2. landmarks
    landmarks_kernel<<<dim3(BH, 8), 256>>>();
    // 3. A softmax + sums  ||  Bv = P @ v   (concurrent blocks)
    AB_kernel<<<32, 256, AB_SMEM>>>();
    // 4. pinv + zB
    pinv_kernel<<<BH, 256, PINV_SMEM>>>();
    // 5. y = softmax(q@kl^T) @ zB  (tensor cores)
    FY_kernel<<<dim3(TT / 64, BH), 256, FY_SMEM>>>();
    // 6. out = y @ w_proj + b_proj
    mma_gemm<1><<<dim3(EE / 128, BB * TT / 128), 256, GEMM_SMEM>>>(b_proj, out, EE);
}

// round 8
// speedup vs baseline: 3.9019x; 1.1182x over previous
#include <cuda_runtime.h>
#include <cuda_bf16.h>
#include <math.h>
#include <stdint.h>

// Problem constants
#define BB 2
#define TT 2048
#define EE 512
#define HH 8
#define HD 64
#define MM 64
#define LL 32
#define BH (BB*HH)
#define NCHUNK 16

// Scratch (device globals; no runtime allocation)
__device__ float g_qkv[BB*TT*3*EE];      // 24 MB (plain [4096][1536])
__device__ float g_xr[BB*TT*EE];         // x in frag-A order, tf32-rounded
__device__ float g_qland[BH*MM*HD];
__device__ float g_kland[BH*MM*HD];
__device__ float g_A[BH*MM*MM];
__device__ float g_Bv[BH*MM*HD];
__device__ float g_sums[BH*2];
__device__ float g_zB[BH*MM*HD];
__device__ float g_y[BB*TT*EE];          // y in frag-A order, tf32-rounded
__device__ float g_wqkvT[3*EE*EE];       // w_qkv in frag-B order, rounded
__device__ float g_wprojT[EE*EE];        // w_proj in frag-B order, rounded

// Frag-A layout (rows R x 512): chunk(rt,c)=rt*16+c holds 128x32; within:
//   float4 idx f=(mb*4+kk)*32+lane -> elems [(grp,tig),(grp+8,tig),(grp,tig+4),(grp+8,tig+4)]
//   of subtile rows rt*128+mb*16, cols c*32+kk*8. (grp=lane>>2, tig=lane&3)
// Frag-B layout (BT rows N x 512): chunk(ntile,c); float2 idx f=(nb*4+kk)*32+lane
//   -> [(n=nb*8+grp, k=kk*8+tig), (same n, k+4)]

__device__ __forceinline__ uint32_t tf32r(float x) {
    uint32_t r; asm("cvt.rna.tf32.f32 %0, %1;" : "=r"(r) : "f"(x)); return r;
}
__device__ __forceinline__ float tf32f(float x) {
    return __uint_as_float(tf32r(x));
}
__device__ __forceinline__ uint32_t smem_u32(const void* p) {
    uint32_t a;
    asm("{ .reg .u64 t; cvta.to.shared.u64 t, %1; cvt.u32.u64 %0, t; }" : "=r"(a) : "l"(p));
    return a;
}
__device__ __forceinline__ void cp16(uint32_t s, const void* g) {
    asm volatile("cp.async.cg.shared.global [%0], [%1], 16;" :: "r"(s), "l"(g));
}
#define CP_COMMIT() asm volatile("cp.async.commit_group;" ::: "memory")
#define CP_WAIT(n)  asm volatile("cp.async.wait_group %0;" :: "n"(n) : "memory")

__device__ __forceinline__ void mma_tf32(float* d, const uint32_t* a,
                                         const uint32_t* b, const float* c) {
    asm volatile(
        "mma.sync.aligned.m16n8k8.row.col.f32.tf32.tf32.f32 "
        "{%0,%1,%2,%3}, {%4,%5,%6,%7}, {%8,%9}, {%10,%11,%12,%13};"
        : "=f"(d[0]), "=f"(d[1]), "=f"(d[2]), "=f"(d[3])
        : "r"(a[0]), "r"(a[1]), "r"(a[2]), "r"(a[3]),
          "r"(b[0]), "r"(b[1]),
          "f"(c[0]), "f"(c[1]), "f"(c[2]), "f"(c[3]));
}

// ---------------------------------------------------------------------------
// prep_kernel: blocks 0..511 permute+round x -> g_xr (frag-A);
//              512..703 w_qkv -> g_wqkvT (frag-B, transposed);
//              704..767 w_proj -> g_wprojT.
// ---------------------------------------------------------------------------
__global__ __launch_bounds__(256)
void prep_kernel(const float* __restrict__ x, const float* __restrict__ wqkv,
                 const float* __restrict__ wproj) {
    __shared__ float t[128 * 36];   // >= 32*132
    int bid = blockIdx.x, tid = threadIdx.x;
    if (bid < 512) {
        int ch = bid, rt = ch >> 4, c = ch & 15;
        #pragma unroll
        for (int i = 0; i < 4; i++) {
            int s = tid + i * 256, r = s >> 3, c4 = (s & 7) * 4;
            float4 v = *(const float4*)(x + (size_t)(rt * 128 + r) * 512 + c * 32 + c4);
            t[r * 36 + c4] = v.x; t[r * 36 + c4 + 1] = v.y;
            t[r * 36 + c4 + 2] = v.z; t[r * 36 + c4 + 3] = v.w;
        }
        __syncthreads();
        #pragma unroll
        for (int i = 0; i < 4; i++) {
            int f = tid + i * 256;
            int lane = f & 31, kk = (f >> 5) & 3, mb = f >> 7;
            int grp = lane >> 2, tig = lane & 3;
            int rr = mb * 16 + grp, cc = kk * 8 + tig;
            float4 o;
            o.x = tf32f(t[rr * 36 + cc]);
            o.y = tf32f(t[(rr + 8) * 36 + cc]);
            o.z = tf32f(t[rr * 36 + cc + 4]);
            o.w = tf32f(t[(rr + 8) * 36 + cc + 4]);
            *(float4*)(g_xr + (size_t)ch * 4096 + f * 4) = o;
        }
    } else {
        const float* w; float* dst; int N, ch;
        if (bid < 704) { w = wqkv; dst = g_wqkvT; N = 1536; ch = bid - 512; }
        else           { w = wproj; dst = g_wprojT; N = 512;  ch = bid - 704; }
        int ntile = ch >> 4, c = ch & 15;
        #pragma unroll
        for (int i = 0; i < 4; i++) {
            int s = tid + i * 256, kr = s >> 5, n4 = (s & 31) * 4;
            float4 v = *(const float4*)(w + (size_t)(c * 32 + kr) * N + ntile * 128 + n4);
            t[kr * 132 + n4] = v.x; t[kr * 132 + n4 + 1] = v.y;
            t[kr * 132 + n4 + 2] = v.z; t[kr * 132 + n4 + 3] = v.w;
        }
        __syncthreads();
        #pragma unroll
        for (int i = 0; i < 8; i++) {
            int f = tid + i * 256;
            int lane = f & 31, kk = (f >> 5) & 3, nb = f >> 7;
            int grp = lane >> 2, tig = lane & 3;
            int nn = nb * 8 + grp, kx = kk * 8 + tig;
            float2 o;
            o.x = tf32f(t[kx * 132 + nn]);
            o.y = tf32f(t[(kx + 4) * 132 + nn]);
            *(float2*)(dst + (size_t)ch * 4096 + f * 2) = o;
        }
    }
}

// ---------------------------------------------------------------------------
// TF32 mma.sync GEMM, frag-order operands, 3-stage cp.async pipeline.
//   C[4096, Nd] = A @ BT^T + bias.  MODE 0: xr/wqkvT->g_qkv; 1: y/wprojT->out.
// CTA 128x128, 256 threads, warp 64x32. Dyn smem 96KB.
// ---------------------------------------------------------------------------
template<int MODE>
__global__ __launch_bounds__(256)
void mma_gemm(const float* __restrict__ bias, float* __restrict__ Cout, int Nd) {
    extern __shared__ float sm[];
    uint32_t sbase = smem_u32(sm);

    const float* A  = (MODE == 0) ? g_xr : g_y;
    const float* BT = (MODE == 0) ? g_wqkvT : g_wprojT;
    float* C = (MODE == 0) ? g_qkv : Cout;

    int tid = threadIdx.x, wid = tid >> 5, lane = tid & 31;
    int bx = blockIdx.x, by = blockIdx.y;
    int wmb = (wid >> 2) * 4;   // m-block base (16-row units)
    int wnb = (wid & 3) * 4;    // n-block base (8-col units)
    int grp = lane >> 2, tig = lane & 3;

    const float* Abase = A  + (size_t)by * 16 * 4096;
    const float* Bbase = BT + (size_t)bx * 16 * 4096;

    float acc[4][4][4];
    #pragma unroll
    for (int mt = 0; mt < 4; mt++)
        #pragma unroll
        for (int nt = 0; nt < 4; nt++)
            #pragma unroll
            for (int r = 0; r < 4; r++) acc[mt][nt][r] = 0.f;

    auto load_chunk = [&](int c, int s) {
        uint32_t a_s = sbase + (uint32_t)(s * 4096) * 4;
        uint32_t b_s = sbase + (uint32_t)((3 + s) * 4096) * 4;
        const float* ag = Abase + c * 4096;
        const float* bg = Bbase + c * 4096;
        #pragma unroll
        for (int i = 0; i < 4; i++) {
            int o = (tid + i * 256) * 4;   // float offset
            cp16(a_s + o * 4, ag + o);
            cp16(b_s + o * 4, bg + o);
        }
    };

    load_chunk(0, 0); CP_COMMIT();
    load_chunk(1, 1); CP_COMMIT();

    int s = 0;
    for (int c = 0; c < NCHUNK; c++) {
        CP_WAIT(1);
        __syncthreads();
        if (c + 2 < NCHUNK) load_chunk(c + 2, (s + 2) % 3);
        CP_COMMIT();   // possibly empty group: keeps wait count uniform

        const float4* As4 = (const float4*)(sm + s * 4096);
        const float2* Bs2 = (const float2*)(sm + (3 + s) * 4096);

        #pragma unroll
        for (int kk = 0; kk < 4; kk++) {
            float4 af[4]; float2 bf[4];
            #pragma unroll
            for (int mt = 0; mt < 4; mt++)
                af[mt] = As4[((wmb + mt) * 4 + kk) * 32 + lane];
            #pragma unroll
            for (int nt = 0; nt < 4; nt++)
                bf[nt] = Bs2[((wnb + nt) * 4 + kk) * 32 + lane];
            #pragma unroll
            for (int mt = 0; mt < 4; mt++)
                #pragma unroll
                for (int nt = 0; nt < 4; nt++)
                    mma_tf32(acc[mt][nt], (const uint32_t*)&af[mt],
                             (const uint32_t*)&bf[nt], acc[mt][nt]);
        }
        s = (s + 1) % 3;
    }

    #pragma unroll
    for (int mt = 0; mt < 4; mt++) {
        int row0 = by * 128 + (wmb + mt) * 16 + grp;
        #pragma unroll
        for (int nt = 0; nt < 4; nt++) {
            int col0 = bx * 128 + (wnb + nt) * 8 + tig * 2;
            float b0 = bias[col0], b1 = bias[col0 + 1];
            float2 o0 = make_float2(acc[mt][nt][0] + b0, acc[mt][nt][1] + b1);
            float2 o1 = make_float2(acc[mt][nt][2] + b0, acc[mt][nt][3] + b1);
            *(float2*)(C + (size_t)row0 * Nd + col0) = o0;
            *(float2*)(C + (size_t)(row0 + 8) * Nd + col0) = o1;
        }
    }
}
#define GEMM_SMEM (6 * 4096 * 4)   // 98304 B

// ---------------------------------------------------------------------------
// Landmarks: grid (BH, 8), one warp per landmark row.
// ---------------------------------------------------------------------------
__global__ __launch_bounds__(256)
void landmarks_kernel() {
    int bh = blockIdx.x;
    int b = bh / HH, h = bh % HH;
    int w = threadIdx.x >> 5, lane = threadIdx.x & 31;
    int m = blockIdx.y * 8 + w;

    float sq0 = 0.f, sq1 = 0.f, sk0 = 0.f, sk1 = 0.f;
    size_t base = ((size_t)(b * TT + m * LL)) * (3 * EE) + h * HD;
    #pragma unroll 4
    for (int g = 0; g < LL; g++) {
        const float* row = g_qkv + base + (size_t)g * 3 * EE;
        sq0 += row[lane];
        sq1 += row[lane + 32];
        sk0 += row[EE + lane];
        sk1 += row[EE + lane + 32];
    }
    float* qo = g_qland + (bh * MM + m) * HD;
    float* ko = g_kland + (bh * MM + m) * HD;
    qo[lane]      = sq0 * (1.0f / LL) * 0.125f;
    qo[lane + 32] = sq1 * (1.0f / LL) * 0.125f;
    ko[lane]      = sk0 * (1.0f / LL);
    ko[lane + 32] = sk1 * (1.0f / LL);
}

// ---------------------------------------------------------------------------
// AB_kernel, grid 32: blocks 0..15 A-softmax+sums; 16..31 Bv = P @ v[:64].
// ---------------------------------------------------------------------------
__global__ __launch_bounds__(256)
void AB_kernel() {
    extern __shared__ float sb[];
    float* kt = sb;
    float* S  = sb + 4096;
    float* B3 = sb + 8192;
    float* cbuf = sb + 12288;
    float* rbuf = sb + 12352;

    int part = blockIdx.x >> 4;
    int bh = blockIdx.x & 15;
    int b = bh / HH, h = bh % HH;
    int tid = threadIdx.x;

    for (int idx = tid; idx < 4096; idx += 256) {
        int j = idx >> 6, d = idx & 63;
        float v = (part == 0)
            ? g_kland[bh * 4096 + j * 64 + d]
            : g_qkv[((size_t)(b * TT + j)) * 3 * EE + EE + h * HD + d];
        kt[d * 64 + ((j + d) & 63)] = v;
    }
    __syncthreads();

    const float* ql = g_qland + bh * 4096;
    for (int idx = tid; idx < 4096; idx += 256) {
        int i = idx >> 6, j = idx & 63;
        if (j <= i) {
            float s = 0.f;
            #pragma unroll 8
            for (int d = 0; d < 64; d++) s += ql[i * 64 + d] * kt[d * 64 + ((j + d) & 63)];
            S[idx] = s;
        } else {
            S[idx] = -INFINITY;
        }
    }
    __syncthreads();

    int w = tid / 32, lane = tid % 32;
    for (int r = 0; r < 8; r++) {
        int i = w * 8 + r;
        float v0 = S[i * 64 + lane], v1 = S[i * 64 + lane + 32];
        float mx = fmaxf(v0, v1);
        for (int o = 16; o > 0; o >>= 1) mx = fmaxf(mx, __shfl_xor_sync(0xffffffffu, mx, o));
        float e0 = expf(v0 - mx), e1 = expf(v1 - mx);
        float sm = e0 + e1;
        for (int o = 16; o > 0; o >>= 1) sm += __shfl_xor_sync(0xffffffffu, sm, o);
        float inv = 1.0f / sm;
        S[i * 64 + lane] = e0 * inv;
        S[i * 64 + lane + 32] = e1 * inv;
    }
    __syncthreads();

    if (part == 0) {
        for (int idx = tid; idx < 4096; idx += 256) g_A[bh * 4096 + idx] = S[idx];
        if (tid < 64) {
            float cs = 0.f, rs = 0.f;
            for (int i = 0; i < 64; i++) { cs += S[i * 64 + tid]; rs += S[tid * 64 + i]; }
            cbuf[tid] = cs; rbuf[tid] = rs;
        }
        __syncthreads();
        if (tid == 0) {
            float cm = cbuf[0], rm = rbuf[0];
            for (int i = 1; i < 64; i++) { cm = fmaxf(cm, cbuf[i]); rm = fmaxf(rm, rbuf[i]); }
            g_sums[bh * 2 + 0] = cm;
            g_sums[bh * 2 + 1] = rm;
        }
    } else {
        for (int idx = tid; idx < 4096; idx += 256) {
            int j = idx >> 6, d = idx & 63;
            kt[j * 64 + d] = g_qkv[((size_t)(b * TT + j)) * 3 * EE + 2 * EE + h * HD + d];
        }
        __syncthreads();
        for (int idx = tid; idx < 4096; idx += 256) {
            int i = idx >> 6, d = idx & 63;
            float s = 0.f;
            #pragma unroll 8
            for (int k = 0; k < 64; k++) s += S[i * 64 + k] * kt[k * 64 + d];
            B3[idx] = s;
        }
        __syncthreads();
        for (int idx = tid; idx < 4096; idx += 256) g_Bv[bh * 4096 + idx] = B3[idx];
    }
}
#define AB_SMEM ((3 * 4096 + 128) * 4)

// ---------------------------------------------------------------------------
// Tensor-core 64x64 matmul on PS-padded smem. C = scale * L @ R' with
// R' = (NEG ? dc*I - R : R); R stored [k][n]. RNDOUT rounds C to tf32.
// ---------------------------------------------------------------------------
#define PS 68

template<bool NEG, bool RNDOUT>
__device__ __forceinline__ void mmtc(float* __restrict__ C,
                                     const float* __restrict__ L,
                                     const float* __restrict__ R,
                                     float dc, float scale) {
    int wid = threadIdx.x >> 5, lane = threadIdx.x & 31;
    int grp = lane >> 2, tig = lane & 3;
    int m0 = (wid & 3) * 16, n0 = (wid >> 2) * 32;

    float acc[4][4];
    #pragma unroll
    for (int nt = 0; nt < 4; nt++)
        #pragma unroll
        for (int r = 0; r < 4; r++) acc[nt][r] = 0.f;

    #pragma unroll
    for (int kk = 0; kk < 64; kk += 8) {
        uint32_t a[4];
        a[0] = __float_as_uint(L[(m0 + grp) * PS + kk + tig]);
        a[1] = __float_as_uint(L[(m0 + grp + 8) * PS + kk + tig]);
        a[2] = __float_as_uint(L[(m0 + grp) * PS + kk + tig + 4]);
        a[3] = __float_as_uint(L[(m0 + grp + 8) * PS + kk + tig + 4]);
        #pragma unroll
        for (int nt = 0; nt < 4; nt++) {
            int n = n0 + nt * 8 + grp;
            float b0v = R[(kk + tig) * PS + n];
            float b1v = R[(kk + tig + 4) * PS + n];
            uint32_t b[2];
            if (NEG) {
                b0v = ((kk + tig) == n ? dc : 0.f) - b0v;
                b1v = ((kk + tig + 4) == n ? dc : 0.f) - b1v;
                b[0] = tf32r(b0v);
                b[1] = tf32r(b1v);
            } else {
                b[0] = __float_as_uint(b0v);
                b[1] = __float_as_uint(b1v);
            }
            mma_tf32(acc[nt], a, b, acc[nt]);
        }
    }

    #pragma unroll
    for (int nt = 0; nt < 4; nt++) {
        int c0 = n0 + nt * 8 + tig * 2;
        float o0 = acc[nt][0] * scale, o1 = acc[nt][1] * scale;
        float o2 = acc[nt][2] * scale, o3 = acc[nt][3] * scale;
        if (RNDOUT) { o0 = tf32f(o0); o1 = tf32f(o1); o2 = tf32f(o2); o3 = tf32f(o3); }
        C[(m0 + grp) * PS + c0]         = o0;
        C[(m0 + grp) * PS + c0 + 1]     = o1;
        C[(m0 + grp + 8) * PS + c0]     = o2;
        C[(m0 + grp + 8) * PS + c0 + 1] = o3;
    }
    __syncthreads();
}

// ---------------------------------------------------------------------------
// pinv + zB fused.
// ---------------------------------------------------------------------------
__global__ __launch_bounds__(256)
void pinv_kernel() {
    extern __shared__ float sm[];
    float* As = sm;
    float* W0 = sm + 1 * 64 * PS;
    float* W1 = sm + 2 * 64 * PS;
    float* W2 = sm + 3 * 64 * PS;
    float* W3 = sm + 4 * 64 * PS;

    int bh = blockIdx.x;
    int tid = threadIdx.x;

    float cm = 0.f, rm = 0.f;
    #pragma unroll
    for (int i = 0; i < BH; i++) {
        cm = fmaxf(cm, g_sums[2 * i + 0]);
        rm = fmaxf(rm, g_sums[2 * i + 1]);
    }
    float inv = 1.0f / (cm * rm);

    const float* Ag = g_A + bh * 4096;
    for (int idx = tid; idx < 4096; idx += 256) {
        int i = idx >> 6, j = idx & 63;
        As[i * PS + j] = tf32f(Ag[idx]);
    }
    __syncthreads();
    for (int idx = tid; idx < 4096; idx += 256) {
        int i = idx >> 6, j = idx & 63;
        W0[i * PS + j] = tf32f(As[j * PS + i] * inv);
    }
    __syncthreads();

    float* z = W0;
    float* x = W1;
    for (int it = 0; it < 6; it++) {
        mmtc<false, true>(x,  As, z,  0.f,  1.0f);
        mmtc<true,  true>(W2, x,  x,  7.f,  1.0f);
        mmtc<true,  true>(W3, x,  W2, 15.f, 1.0f);
        mmtc<true,  true>(x,  z,  W3, 13.f, 0.25f);
        float* tmp = z; z = x; x = tmp;
    }

    float* Bvs = (z == W0) ? W1 : W0;
    for (int idx = tid; idx < 4096; idx += 256) {
        int i = idx >> 6, j = idx & 63;
        Bvs[i * PS + j] = tf32f(g_Bv[bh * 4096 + idx]);
    }
    __syncthreads();
    mmtc<false, false>(W3, z, Bvs, 0.f, 1.0f);

    for (int idx = tid; idx < 4096; idx += 256) {
        int i = idx >> 6, j = idx & 63;
        g_zB[bh * 4096 + idx] = W3[i * PS + j];
    }
}
#define PINV_SMEM (5 * 64 * PS * 4)

// ---------------------------------------------------------------------------
// Fused F@zB with tensor cores; writes y in frag-A order (tf32-rounded).
// ---------------------------------------------------------------------------
__global__ __launch_bounds__(256)
void FY_kernel() {
    extern __shared__ float sb[];
    float* ks = sb;
    float* qs = sb + 64 * PS;
    float* Ss = sb + 2 * 64 * PS;
    int tt = blockIdx.x, bh = blockIdx.y;
    int b = bh / HH, h = bh % HH;
    int tid = threadIdx.x;

    for (int idx = tid; idx < 4096; idx += 256) {
        int j = idx >> 6, d = idx & 63;
        ks[d * PS + j] = tf32f(g_kland[bh * 4096 + j * 64 + d]);
    }
    for (int idx = tid; idx < 4096; idx += 256) {
        int r = idx >> 6, d = idx & 63;
        qs[r * PS + d] = tf32f(g_qkv[((size_t)(b * TT + tt * 64 + r)) * 3 * EE + h * HD + d] * 0.125f);
    }
    __syncthreads();

    mmtc<false, false>(Ss, qs, ks, 0.f, 1.0f);

    int w = tid / 32, lane = tid % 32;
    for (int r = 0; r < 8; r++) {
        int row = w * 8 + r;
        int t = tt * 64 + row;
        float a0 = Ss[row * PS + lane];
        float a1 = Ss[row * PS + lane + 32];
        if (lane > t) a0 = -INFINITY;
        if (lane + 32 > t) a1 = -INFINITY;
        float mx = fmaxf(a0, a1);
        for (int o = 16; o > 0; o >>= 1) mx = fmaxf(mx, __shfl_xor_sync(0xffffffffu, mx, o));
        float e0 = expf(a0 - mx), e1 = expf(a1 - mx);
        float sm = e0 + e1;
        for (int o = 16; o > 0; o >>= 1) sm += __shfl_xor_sync(0xffffffffu, sm, o);
        float inv = 1.0f / sm;
        Ss[row * PS + lane] = tf32f(e0 * inv);
        Ss[row * PS + lane + 32] = tf32f(e1 * inv);
    }
    __syncthreads();

    for (int idx = tid; idx < 4096; idx += 256) {
        int m = idx >> 6, d = idx & 63;
        ks[m * PS + d] = tf32f(g_zB[bh * 4096 + idx]);
    }
    __syncthreads();

    mmtc<false, false>(qs, Ss, ks, 0.f, 1.0f);

    // write Y -> g_y in frag-A order (rounded), fully coalesced STG.128
    int rt = (b * TT + tt * 64) >> 7;
    int mb0 = (tt & 1) * 4;
    #pragma unroll
    for (int c_off = 0; c_off < 2; c_off++) {
        int cch = h * 2 + c_off;
        size_t base_f4 = ((size_t)(rt * 16 + cch)) * 1024 + mb0 * 128;
        #pragma unroll
        for (int i = 0; i < 2; i++) {
            int u = tid + i * 256;
            int lane2 = u & 31, kk = (u >> 5) & 3, mbr = u >> 7;
            int grp = lane2 >> 2, tig = lane2 & 3;
            int rl = mbr * 16 + grp;
            int dd = c_off * 32 + kk * 8 + tig;
            float4 o;
            o.x = tf32f(qs[rl * PS + dd]);
            o.y = tf32f(qs[(rl + 8) * PS + dd]);
            o.z = tf32f(qs[rl * PS + dd + 4]);
            o.w = tf32f(qs[(rl + 8) * PS + dd + 4]);
            *(float4*)(g_y + (base_f4 + u) * 4) = o;
        }
    }
}
#define FY_SMEM (3 * 64 * PS * 4)

// ---------------------------------------------------------------------------
extern "C" void kernel_launch(void* const* d_in, const int* in_sizes, int n_in,
                              void* d_out, int out_size) {
    const float* x      = (const float*)d_in[0];
    const float* w_qkv  = (const float*)d_in[1];
    const float* b_qkv  = (const float*)d_in[2];
    const float* w_proj = (const float*)d_in[3];
    const float* b_proj = (const float*)d_in[4];
    float* out = (float*)d_out;

    cudaFuncSetAttribute(pinv_kernel,
                         cudaFuncAttributeMaxDynamicSharedMemorySize, PINV_SMEM);
    cudaFuncSetAttribute(mma_gemm<0>,
                         cudaFuncAttributeMaxDynamicSharedMemorySize, GEMM_SMEM);
    cudaFuncSetAttribute(mma_gemm<1>,
                         cudaFuncAttributeMaxDynamicSharedMemorySize, GEMM_SMEM);
    cudaFuncSetAttribute(AB_kernel,
                         cudaFuncAttributeMaxDynamicSharedMemorySize, AB_SMEM);
    cudaFuncSetAttribute(FY_kernel,
                         cudaFuncAttributeMaxDynamicSharedMemorySize, FY_SMEM);

    // 0. permute+round x and weights into fragment order
    prep_kernel<<<768, 256>>>(x, w_qkv, w_proj);
    // 1. qkv = x @ w_qkv + b_qkv
    mma_gemm<0><<<dim3(3 * EE / 128, BB * TT / 128), 256, GEMM_SMEM>>>(b_qkv, nullptr, 3 * EE);
    // 2. landmarks
    landmarks_kernel<<<dim3(BH, 8), 256>>>();
    // 3. A softmax + sums  ||  Bv = P @ v
    AB_kernel<<<32, 256, AB_SMEM>>>();
    // 4. pinv + zB
    pinv_kernel<<<BH, 256, PINV_SMEM>>>();
    // 5. y = softmax(q@kl^T) @ zB  (frag-order writeback)
    FY_kernel<<<dim3(TT / 64, BH), 256, FY_SMEM>>>();
    // 6. out = y @ w_proj + b_proj
    mma_gemm<1><<<dim3(EE / 128, BB * TT / 128), 256, GEMM_SMEM>>>(b_proj, out, EE);
}

// round 9
// speedup vs baseline: 4.6956x; 1.2034x over previous
#include <cuda_runtime.h>
#include <cuda_bf16.h>
#include <math.h>
#include <stdint.h>

// Problem constants
#define BB 2
#define TT 2048
#define EE 512
#define HH 8
#define HD 64
#define MM 64
#define LL 32
#define BH (BB*HH)
#define NCHUNK 16

// Scratch (device globals; no runtime allocation)
__device__ float g_qkv[BB*TT*3*EE];      // 24 MB (plain [4096][1536])
__device__ float g_xr[BB*TT*EE];         // x in frag-A order, tf32-rounded
__device__ float g_qland[BH*MM*HD];
__device__ float g_kland[BH*MM*HD];
__device__ float g_A[BH*MM*MM];
__device__ float g_Bv[BH*MM*HD];
__device__ float g_sums[BH*2];
__device__ float g_zB[BH*MM*HD];
__device__ float g_y[BB*TT*EE];          // y in frag-A order, tf32-rounded
__device__ float g_wqkvT[3*EE*EE];       // w_qkv in frag-B order, rounded
__device__ float g_wprojT[EE*EE];        // w_proj in frag-B order, rounded

__device__ __forceinline__ uint32_t tf32r(float x) {
    uint32_t r; asm("cvt.rna.tf32.f32 %0, %1;" : "=r"(r) : "f"(x)); return r;
}
__device__ __forceinline__ float tf32f(float x) {
    return __uint_as_float(tf32r(x));
}
__device__ __forceinline__ uint32_t smem_u32(const void* p) {
    uint32_t a;
    asm("{ .reg .u64 t; cvta.to.shared.u64 t, %1; cvt.u32.u64 %0, t; }" : "=r"(a) : "l"(p));
    return a;
}
__device__ __forceinline__ void cp16(uint32_t s, const void* g) {
    asm volatile("cp.async.cg.shared.global [%0], [%1], 16;" :: "r"(s), "l"(g));
}
#define CP_COMMIT() asm volatile("cp.async.commit_group;" ::: "memory")
#define CP_WAIT(n)  asm volatile("cp.async.wait_group %0;" :: "n"(n) : "memory")

__device__ __forceinline__ void mma_tf32(float* d, const uint32_t* a,
                                         const uint32_t* b, const float* c) {
    asm volatile(
        "mma.sync.aligned.m16n8k8.row.col.f32.tf32.tf32.f32 "
        "{%0,%1,%2,%3}, {%4,%5,%6,%7}, {%8,%9}, {%10,%11,%12,%13};"
        : "=f"(d[0]), "=f"(d[1]), "=f"(d[2]), "=f"(d[3])
        : "r"(a[0]), "r"(a[1]), "r"(a[2]), "r"(a[3]),
          "r"(b[0]), "r"(b[1]),
          "f"(c[0]), "f"(c[1]), "f"(c[2]), "f"(c[3]));
}

// ---------------------------------------------------------------------------
// prep_kernel: blocks 0..511 permute+round x -> g_xr (frag-A);
//              512..703 w_qkv -> g_wqkvT (frag-B); 704..767 w_proj -> g_wprojT.
// ---------------------------------------------------------------------------
__global__ __launch_bounds__(256)
void prep_kernel(const float* __restrict__ x, const float* __restrict__ wqkv,
                 const float* __restrict__ wproj) {
    __shared__ float t[128 * 36];   // >= 32*132
    int bid = blockIdx.x, tid = threadIdx.x;
    if (bid < 512) {
        int ch = bid, rt = ch >> 4, c = ch & 15;
        #pragma unroll
        for (int i = 0; i < 4; i++) {
            int s = tid + i * 256, r = s >> 3, c4 = (s & 7) * 4;
            float4 v = *(const float4*)(x + (size_t)(rt * 128 + r) * 512 + c * 32 + c4);
            t[r * 36 + c4] = v.x; t[r * 36 + c4 + 1] = v.y;
            t[r * 36 + c4 + 2] = v.z; t[r * 36 + c4 + 3] = v.w;
        }
        __syncthreads();
        #pragma unroll
        for (int i = 0; i < 4; i++) {
            int f = tid + i * 256;
            int lane = f & 31, kk = (f >> 5) & 3, mb = f >> 7;
            int grp = lane >> 2, tig = lane & 3;
            int rr = mb * 16 + grp, cc = kk * 8 + tig;
            float4 o;
            o.x = tf32f(t[rr * 36 + cc]);
            o.y = tf32f(t[(rr + 8) * 36 + cc]);
            o.z = tf32f(t[rr * 36 + cc + 4]);
            o.w = tf32f(t[(rr + 8) * 36 + cc + 4]);
            *(float4*)(g_xr + (size_t)ch * 4096 + f * 4) = o;
        }
    } else {
        const float* w; float* dst; int N, ch;
        if (bid < 704) { w = wqkv; dst = g_wqkvT; N = 1536; ch = bid - 512; }
        else           { w = wproj; dst = g_wprojT; N = 512;  ch = bid - 704; }
        int ntile = ch >> 4, c = ch & 15;
        #pragma unroll
        for (int i = 0; i < 4; i++) {
            int s = tid + i * 256, kr = s >> 5, n4 = (s & 31) * 4;
            float4 v = *(const float4*)(w + (size_t)(c * 32 + kr) * N + ntile * 128 + n4);
            t[kr * 132 + n4] = v.x; t[kr * 132 + n4 + 1] = v.y;
            t[kr * 132 + n4 + 2] = v.z; t[kr * 132 + n4 + 3] = v.w;
        }
        __syncthreads();
        #pragma unroll
        for (int i = 0; i < 8; i++) {
            int f = tid + i * 256;
            int lane = f & 31, kk = (f >> 5) & 3, nb = f >> 7;
            int grp = lane >> 2, tig = lane & 3;
            int nn = nb * 8 + grp, kx = kk * 8 + tig;
            float2 o;
            o.x = tf32f(t[kx * 132 + nn]);
            o.y = tf32f(t[(kx + 4) * 132 + nn]);
            *(float2*)(dst + (size_t)ch * 4096 + f * 2) = o;
        }
    }
}

// ---------------------------------------------------------------------------
// TF32 mma.sync GEMM, frag-order operands, 3-stage cp.async pipeline.
// ---------------------------------------------------------------------------
template<int MODE>
__global__ __launch_bounds__(256)
void mma_gemm(const float* __restrict__ bias, float* __restrict__ Cout, int Nd) {
    extern __shared__ float sm[];
    uint32_t sbase = smem_u32(sm);

    const float* A  = (MODE == 0) ? g_xr : g_y;
    const float* BT = (MODE == 0) ? g_wqkvT : g_wprojT;
    float* C = (MODE == 0) ? g_qkv : Cout;

    int tid = threadIdx.x, wid = tid >> 5, lane = tid & 31;
    int bx = blockIdx.x, by = blockIdx.y;
    int wmb = (wid >> 2) * 4;
    int wnb = (wid & 3) * 4;
    int grp = lane >> 2, tig = lane & 3;

    const float* Abase = A  + (size_t)by * 16 * 4096;
    const float* Bbase = BT + (size_t)bx * 16 * 4096;

    float acc[4][4][4];
    #pragma unroll
    for (int mt = 0; mt < 4; mt++)
        #pragma unroll
        for (int nt = 0; nt < 4; nt++)
            #pragma unroll
            for (int r = 0; r < 4; r++) acc[mt][nt][r] = 0.f;

    auto load_chunk = [&](int c, int s) {
        uint32_t a_s = sbase + (uint32_t)(s * 4096) * 4;
        uint32_t b_s = sbase + (uint32_t)((3 + s) * 4096) * 4;
        const float* ag = Abase + c * 4096;
        const float* bg = Bbase + c * 4096;
        #pragma unroll
        for (int i = 0; i < 4; i++) {
            int o = (tid + i * 256) * 4;
            cp16(a_s + o * 4, ag + o);
            cp16(b_s + o * 4, bg + o);
        }
    };

    load_chunk(0, 0); CP_COMMIT();
    load_chunk(1, 1); CP_COMMIT();

    int s = 0;
    for (int c = 0; c < NCHUNK; c++) {
        CP_WAIT(1);
        __syncthreads();
        if (c + 2 < NCHUNK) load_chunk(c + 2, (s + 2) % 3);
        CP_COMMIT();

        const float4* As4 = (const float4*)(sm + s * 4096);
        const float2* Bs2 = (const float2*)(sm + (3 + s) * 4096);

        #pragma unroll
        for (int kk = 0; kk < 4; kk++) {
            float4 af[4]; float2 bf[4];
            #pragma unroll
            for (int mt = 0; mt < 4; mt++)
                af[mt] = As4[((wmb + mt) * 4 + kk) * 32 + lane];
            #pragma unroll
            for (int nt = 0; nt < 4; nt++)
                bf[nt] = Bs2[((wnb + nt) * 4 + kk) * 32 + lane];
            #pragma unroll
            for (int mt = 0; mt < 4; mt++)
                #pragma unroll
                for (int nt = 0; nt < 4; nt++)
                    mma_tf32(acc[mt][nt], (const uint32_t*)&af[mt],
                             (const uint32_t*)&bf[nt], acc[mt][nt]);
        }
        s = (s + 1) % 3;
    }

    #pragma unroll
    for (int mt = 0; mt < 4; mt++) {
        int row0 = by * 128 + (wmb + mt) * 16 + grp;
        #pragma unroll
        for (int nt = 0; nt < 4; nt++) {
            int col0 = bx * 128 + (wnb + nt) * 8 + tig * 2;
            float b0 = bias[col0], b1 = bias[col0 + 1];
            float2 o0 = make_float2(acc[mt][nt][0] + b0, acc[mt][nt][1] + b1);
            float2 o1 = make_float2(acc[mt][nt][2] + b0, acc[mt][nt][3] + b1);
            *(float2*)(C + (size_t)row0 * Nd + col0) = o0;
            *(float2*)(C + (size_t)(row0 + 8) * Nd + col0) = o1;
        }
    }
}
#define GEMM_SMEM (6 * 4096 * 4)   // 98304 B

// ---------------------------------------------------------------------------
// Landmarks: grid (BH, 8), one warp per landmark row.
// ---------------------------------------------------------------------------
__global__ __launch_bounds__(256)
void landmarks_kernel() {
    int bh = blockIdx.x;
    int b = bh / HH, h = bh % HH;
    int w = threadIdx.x >> 5, lane = threadIdx.x & 31;
    int m = blockIdx.y * 8 + w;

    float sq0 = 0.f, sq1 = 0.f, sk0 = 0.f, sk1 = 0.f;
    size_t base = ((size_t)(b * TT + m * LL)) * (3 * EE) + h * HD;
    #pragma unroll 4
    for (int g = 0; g < LL; g++) {
        const float* row = g_qkv + base + (size_t)g * 3 * EE;
        sq0 += row[lane];
        sq1 += row[lane + 32];
        sk0 += row[EE + lane];
        sk1 += row[EE + lane + 32];
    }
    float* qo = g_qland + (bh * MM + m) * HD;
    float* ko = g_kland + (bh * MM + m) * HD;
    qo[lane]      = sq0 * (1.0f / LL) * 0.125f;
    qo[lane + 32] = sq1 * (1.0f / LL) * 0.125f;
    ko[lane]      = sk0 * (1.0f / LL);
    ko[lane + 32] = sk1 * (1.0f / LL);
}

// ---------------------------------------------------------------------------
// Tensor-core 64x64 matmul on PS-padded smem. C = scale * L @ R' with
// R' = (NEG ? dc*I - R : R); R stored [k][n]. RNDOUT rounds C to tf32.
// ---------------------------------------------------------------------------
#define PS 68

template<bool NEG, bool RNDOUT>
__device__ __forceinline__ void mmtc(float* __restrict__ C,
                                     const float* __restrict__ L,
                                     const float* __restrict__ R,
                                     float dc, float scale) {
    int wid = threadIdx.x >> 5, lane = threadIdx.x & 31;
    int grp = lane >> 2, tig = lane & 3;
    int m0 = (wid & 3) * 16, n0 = (wid >> 2) * 32;

    float acc[4][4];
    #pragma unroll
    for (int nt = 0; nt < 4; nt++)
        #pragma unroll
        for (int r = 0; r < 4; r++) acc[nt][r] = 0.f;

    #pragma unroll
    for (int kk = 0; kk < 64; kk += 8) {
        uint32_t a[4];
        a[0] = __float_as_uint(L[(m0 + grp) * PS + kk + tig]);
        a[1] = __float_as_uint(L[(m0 + grp + 8) * PS + kk + tig]);
        a[2] = __float_as_uint(L[(m0 + grp) * PS + kk + tig + 4]);
        a[3] = __float_as_uint(L[(m0 + grp + 8) * PS + kk + tig + 4]);
        #pragma unroll
        for (int nt = 0; nt < 4; nt++) {
            int n = n0 + nt * 8 + grp;
            float b0v = R[(kk + tig) * PS + n];
            float b1v = R[(kk + tig + 4) * PS + n];
            uint32_t b[2];
            if (NEG) {
                b0v = ((kk + tig) == n ? dc : 0.f) - b0v;
                b1v = ((kk + tig + 4) == n ? dc : 0.f) - b1v;
                b[0] = tf32r(b0v);
                b[1] = tf32r(b1v);
            } else {
                b[0] = __float_as_uint(b0v);
                b[1] = __float_as_uint(b1v);
            }
            mma_tf32(acc[nt], a, b, acc[nt]);
        }
    }

    #pragma unroll
    for (int nt = 0; nt < 4; nt++) {
        int c0 = n0 + nt * 8 + tig * 2;
        float o0 = acc[nt][0] * scale, o1 = acc[nt][1] * scale;
        float o2 = acc[nt][2] * scale, o3 = acc[nt][3] * scale;
        if (RNDOUT) { o0 = tf32f(o0); o1 = tf32f(o1); o2 = tf32f(o2); o3 = tf32f(o3); }
        C[(m0 + grp) * PS + c0]         = o0;
        C[(m0 + grp) * PS + c0 + 1]     = o1;
        C[(m0 + grp + 8) * PS + c0]     = o2;
        C[(m0 + grp + 8) * PS + c0 + 1] = o3;
    }
    __syncthreads();
}

// ---------------------------------------------------------------------------
// AB_kernel (tensorized), grid 32, 256 threads, dyn smem ~52KB:
//   blocks 0..15  : A = softmax(mask(ql @ kl^T)) + per-bh sum maxima
//   blocks 16..31 : Bv = softmax(mask(ql @ k[:64]^T)) @ v[:64]
// ---------------------------------------------------------------------------
__global__ __launch_bounds__(256)
void AB_kernel() {
    extern __shared__ float sb[];
    float* qs = sb;               // L: ql rows [i][d]
    float* ks = sb + 64 * PS;     // R: k^T [d][j]; later v [j][d] (part 1)
    float* Ss = sb + 2 * 64 * PS; // logits -> probs
    float* cbuf = sb + 3 * 64 * PS;
    float* rbuf = cbuf + 64;

    int part = blockIdx.x >> 4;
    int bh = blockIdx.x & 15;
    int b = bh / HH, h = bh % HH;
    int tid = threadIdx.x;

    // L = ql (already scaled by 0.125), rounded
    for (int idx = tid; idx < 4096; idx += 256) {
        int i = idx >> 6, d = idx & 63;
        qs[i * PS + d] = tf32f(g_qland[bh * 4096 + idx]);
    }
    // R = kl^T or k[:64]^T, rounded: ks[d][j]
    for (int idx = tid; idx < 4096; idx += 256) {
        int j = idx >> 6, d = idx & 63;
        float v = (part == 0)
            ? g_kland[bh * 4096 + j * 64 + d]
            : g_qkv[((size_t)(b * TT + j)) * 3 * EE + EE + h * HD + d];
        ks[d * PS + j] = tf32f(v);
    }
    __syncthreads();

    // logits = ql @ k^T
    mmtc<false, false>(Ss, qs, ks, 0.f, 1.0f);

    // mask (j <= i) + row softmax
    int w = tid / 32, lane = tid % 32;
    for (int r = 0; r < 8; r++) {
        int i = w * 8 + r;
        float a0 = Ss[i * PS + lane];
        float a1 = Ss[i * PS + lane + 32];
        if (lane > i) a0 = -INFINITY;
        if (lane + 32 > i) a1 = -INFINITY;
        float mx = fmaxf(a0, a1);
        for (int o = 16; o > 0; o >>= 1) mx = fmaxf(mx, __shfl_xor_sync(0xffffffffu, mx, o));
        float e0 = expf(a0 - mx), e1 = expf(a1 - mx);
        float sm = e0 + e1;
        for (int o = 16; o > 0; o >>= 1) sm += __shfl_xor_sync(0xffffffffu, sm, o);
        float inv = 1.0f / sm;
        float p0 = e0 * inv, p1 = e1 * inv;
        if (part == 1) { p0 = tf32f(p0); p1 = tf32f(p1); }   // feeds next mma
        Ss[i * PS + lane] = p0;
        Ss[i * PS + lane + 32] = p1;
    }
    __syncthreads();

    if (part == 0) {
        for (int idx = tid; idx < 4096; idx += 256) {
            int i = idx >> 6, j = idx & 63;
            g_A[bh * 4096 + idx] = Ss[i * PS + j];
        }
        if (tid < 64) {
            float cs = 0.f, rs = 0.f;
            for (int i = 0; i < 64; i++) { cs += Ss[i * PS + tid]; rs += Ss[tid * PS + i]; }
            cbuf[tid] = cs; rbuf[tid] = rs;
        }
        __syncthreads();
        if (tid == 0) {
            float cm = cbuf[0], rm = rbuf[0];
            for (int i = 1; i < 64; i++) { cm = fmaxf(cm, cbuf[i]); rm = fmaxf(rm, rbuf[i]); }
            g_sums[bh * 2 + 0] = cm;
            g_sums[bh * 2 + 1] = rm;
        }
    } else {
        // v[:64] into qs as R layout [k=j][n=d], rounded
        for (int idx = tid; idx < 4096; idx += 256) {
            int j = idx >> 6, d = idx & 63;
            qs[j * PS + d] = tf32f(g_qkv[((size_t)(b * TT + j)) * 3 * EE + 2 * EE + h * HD + d]);
        }
        __syncthreads();
        // Bv = probs @ v  (C=ks is free)
        mmtc<false, false>(ks, Ss, qs, 0.f, 1.0f);
        for (int idx = tid; idx < 4096; idx += 256) {
            int i = idx >> 6, d = idx & 63;
            g_Bv[bh * 4096 + idx] = ks[i * PS + d];
        }
    }
}
#define AB_SMEM ((3 * 64 * PS + 128) * 4)

// ---------------------------------------------------------------------------
// pinv + zB fused.
// ---------------------------------------------------------------------------
__global__ __launch_bounds__(256)
void pinv_kernel() {
    extern __shared__ float sm[];
    float* As = sm;
    float* W0 = sm + 1 * 64 * PS;
    float* W1 = sm + 2 * 64 * PS;
    float* W2 = sm + 3 * 64 * PS;
    float* W3 = sm + 4 * 64 * PS;

    int bh = blockIdx.x;
    int tid = threadIdx.x;

    float cm = 0.f, rm = 0.f;
    #pragma unroll
    for (int i = 0; i < BH; i++) {
        cm = fmaxf(cm, g_sums[2 * i + 0]);
        rm = fmaxf(rm, g_sums[2 * i + 1]);
    }
    float inv = 1.0f / (cm * rm);

    const float* Ag = g_A + bh * 4096;
    for (int idx = tid; idx < 4096; idx += 256) {
        int i = idx >> 6, j = idx & 63;
        As[i * PS + j] = tf32f(Ag[idx]);
    }
    __syncthreads();
    for (int idx = tid; idx < 4096; idx += 256) {
        int i = idx >> 6, j = idx & 63;
        W0[i * PS + j] = tf32f(As[j * PS + i] * inv);
    }
    __syncthreads();

    float* z = W0;
    float* x = W1;
    for (int it = 0; it < 6; it++) {
        mmtc<false, true>(x,  As, z,  0.f,  1.0f);
        mmtc<true,  true>(W2, x,  x,  7.f,  1.0f);
        mmtc<true,  true>(W3, x,  W2, 15.f, 1.0f);
        mmtc<true,  true>(x,  z,  W3, 13.f, 0.25f);
        float* tmp = z; z = x; x = tmp;
    }

    float* Bvs = (z == W0) ? W1 : W0;
    for (int idx = tid; idx < 4096; idx += 256) {
        int i = idx >> 6, j = idx & 63;
        Bvs[i * PS + j] = tf32f(g_Bv[bh * 4096 + idx]);
    }
    __syncthreads();
    mmtc<false, false>(W3, z, Bvs, 0.f, 1.0f);

    for (int idx = tid; idx < 4096; idx += 256) {
        int i = idx >> 6, j = idx & 63;
        g_zB[bh * 4096 + idx] = W3[i * PS + j];
    }
}
#define PINV_SMEM (5 * 64 * PS * 4)

// ---------------------------------------------------------------------------
// Fused F@zB with tensor cores; writes y in frag-A order (tf32-rounded).
// ---------------------------------------------------------------------------
__global__ __launch_bounds__(256)
void FY_kernel() {
    extern __shared__ float sb[];
    float* ks = sb;
    float* qs = sb + 64 * PS;
    float* Ss = sb + 2 * 64 * PS;
    int tt = blockIdx.x, bh = blockIdx.y;
    int b = bh / HH, h = bh % HH;
    int tid = threadIdx.x;

    for (int idx = tid; idx < 4096; idx += 256) {
        int j = idx >> 6, d = idx & 63;
        ks[d * PS + j] = tf32f(g_kland[bh * 4096 + j * 64 + d]);
    }
    for (int idx = tid; idx < 4096; idx += 256) {
        int r = idx >> 6, d = idx & 63;
        qs[r * PS + d] = tf32f(g_qkv[((size_t)(b * TT + tt * 64 + r)) * 3 * EE + h * HD + d] * 0.125f);
    }
    __syncthreads();

    mmtc<false, false>(Ss, qs, ks, 0.f, 1.0f);

    int w = tid / 32, lane = tid % 32;
    for (int r = 0; r < 8; r++) {
        int row = w * 8 + r;
        int t = tt * 64 + row;
        float a0 = Ss[row * PS + lane];
        float a1 = Ss[row * PS + lane + 32];
        if (lane > t) a0 = -INFINITY;
        if (lane + 32 > t) a1 = -INFINITY;
        float mx = fmaxf(a0, a1);
        for (int o = 16; o > 0; o >>= 1) mx = fmaxf(mx, __shfl_xor_sync(0xffffffffu, mx, o));
        float e0 = expf(a0 - mx), e1 = expf(a1 - mx);
        float sm = e0 + e1;
        for (int o = 16; o > 0; o >>= 1) sm += __shfl_xor_sync(0xffffffffu, sm, o);
        float inv = 1.0f / sm;
        Ss[row * PS + lane] = tf32f(e0 * inv);
        Ss[row * PS + lane + 32] = tf32f(e1 * inv);
    }
    __syncthreads();

    for (int idx = tid; idx < 4096; idx += 256) {
        int m = idx >> 6, d = idx & 63;
        ks[m * PS + d] = tf32f(g_zB[bh * 4096 + idx]);
    }
    __syncthreads();

    mmtc<false, false>(qs, Ss, ks, 0.f, 1.0f);

    int rt = (b * TT + tt * 64) >> 7;
    int mb0 = (tt & 1) * 4;
    #pragma unroll
    for (int c_off = 0; c_off < 2; c_off++) {
        int cch = h * 2 + c_off;
        size_t base_f4 = ((size_t)(rt * 16 + cch)) * 1024 + mb0 * 128;
        #pragma unroll
        for (int i = 0; i < 2; i++) {
            int u = tid + i * 256;
            int lane2 = u & 31, kk = (u >> 5) & 3, mbr = u >> 7;
            int grp = lane2 >> 2, tig = lane2 & 3;
            int rl = mbr * 16 + grp;
            int dd = c_off * 32 + kk * 8 + tig;
            float4 o;
            o.x = tf32f(qs[rl * PS + dd]);
            o.y = tf32f(qs[(rl + 8) * PS + dd]);
            o.z = tf32f(qs[rl * PS + dd + 4]);
            o.w = tf32f(qs[(rl + 8) * PS + dd + 4]);
            *(float4*)(g_y + (base_f4 + u) * 4) = o;
        }
    }
}
#define FY_SMEM (3 * 64 * PS * 4)

// ---------------------------------------------------------------------------
extern "C" void kernel_launch(void* const* d_in, const int* in_sizes, int n_in,
                              void* d_out, int out_size) {
    const float* x      = (const float*)d_in[0];
    const float* w_qkv  = (const float*)d_in[1];
    const float* b_qkv  = (const float*)d_in[2];
    const float* w_proj = (const float*)d_in[3];
    const float* b_proj = (const float*)d_in[4];
    float* out = (float*)d_out;

    cudaFuncSetAttribute(pinv_kernel,
                         cudaFuncAttributeMaxDynamicSharedMemorySize, PINV_SMEM);
    cudaFuncSetAttribute(mma_gemm<0>,
                         cudaFuncAttributeMaxDynamicSharedMemorySize, GEMM_SMEM);
    cudaFuncSetAttribute(mma_gemm<1>,
                         cudaFuncAttributeMaxDynamicSharedMemorySize, GEMM_SMEM);
    cudaFuncSetAttribute(AB_kernel,
                         cudaFuncAttributeMaxDynamicSharedMemorySize, AB_SMEM);
    cudaFuncSetAttribute(FY_kernel,
                         cudaFuncAttributeMaxDynamicSharedMemorySize, FY_SMEM);

    // 0. permute+round x and weights into fragment order
    prep_kernel<<<768, 256>>>(x, w_qkv, w_proj);
    // 1. qkv = x @ w_qkv + b_qkv
    mma_gemm<0><<<dim3(3 * EE / 128, BB * TT / 128), 256, GEMM_SMEM>>>(b_qkv, nullptr, 3 * EE);
    // 2. landmarks
    landmarks_kernel<<<dim3(BH, 8), 256>>>();
    // 3. A softmax + sums  ||  Bv = P @ v   (tensorized)
    AB_kernel<<<32, 256, AB_SMEM>>>();
    // 4. pinv + zB
    pinv_kernel<<<BH, 256, PINV_SMEM>>>();
    // 5. y = softmax(q@kl^T) @ zB
    FY_kernel<<<dim3(TT / 64, BH), 256, FY_SMEM>>>();
    // 6. out = y @ w_proj + b_proj
    mma_gemm<1><<<dim3(EE / 128, BB * TT / 128), 256, GEMM_SMEM>>>(b_proj, out, EE);
}